// round 2
// baseline (speedup 1.0000x reference)
#include <cuda_runtime.h>
#include <math.h>

// Problem constants
constexpr int B_   = 16;
constexpr int N_   = 1024;
constexpr int CIN_ = 64;
constexpr int HID_ = 128;
constexpr int H_   = 8;
constexpr int COUT_= 64;
constexpr int CAT_ = HID_ * H_;   // 1024

// Scratch (device globals — no allocation allowed)
__device__ float g_feat[B_ * N_ * CAT_];   // layer-1 per-head features, concat layout [b][n][h*128+d]
__device__ float g_cat [B_ * N_ * CAT_];   // leakyrelu(attn1 + bh) in concat layout
__device__ float g_h2  [B_ * N_ * COUT_];  // layer-2 features

// ---------------------------------------------------------------------------
// Kernel 1: g_feat[bn][h*128+d] = flow_x[bn] @ Wh[h]   (M=16384, K=64, Nc=128)
// ---------------------------------------------------------------------------
__global__ __launch_bounds__(256) void gemm1_kernel(const float* __restrict__ x,
                                                    const float* __restrict__ Wh) {
    __shared__ float sX[64][CIN_];    // 16 KB
    __shared__ float sW[CIN_][HID_];  // 32 KB
    const int tid = threadIdx.x;
    const int tx = tid & 15, ty = tid >> 4;
    const int bn0 = blockIdx.x * 64;
    const int h = blockIdx.y;
    const float* Wp = Wh + (size_t)h * CIN_ * HID_;

    for (int i = tid; i < CIN_ * HID_; i += 256) sW[i / HID_][i % HID_] = Wp[i];
    for (int i = tid; i < 64 * CIN_; i += 256)
        sX[i / CIN_][i % CIN_] = x[(size_t)(bn0 + i / CIN_) * CIN_ + (i % CIN_)];
    __syncthreads();

    float acc[4][8];
#pragma unroll
    for (int i = 0; i < 4; i++)
#pragma unroll
        for (int j = 0; j < 8; j++) acc[i][j] = 0.f;

#pragma unroll 4
    for (int k = 0; k < CIN_; k++) {
        float xv[4], wv[8];
#pragma unroll
        for (int i = 0; i < 4; i++) xv[i] = sX[ty * 4 + i][k];
#pragma unroll
        for (int j = 0; j < 8; j++) wv[j] = sW[k][tx + 16 * j];
#pragma unroll
        for (int i = 0; i < 4; i++)
#pragma unroll
            for (int j = 0; j < 8; j++) acc[i][j] = fmaf(xv[i], wv[j], acc[i][j]);
    }

#pragma unroll
    for (int i = 0; i < 4; i++)
#pragma unroll
        for (int j = 0; j < 8; j++)
            g_feat[(size_t)(bn0 + ty * 4 + i) * CAT_ + h * HID_ + tx + 16 * j] = acc[i][j];
}

// ---------------------------------------------------------------------------
// Fused masked-softmax attention (flash-style), Q=K=V=feat.
//   LAYER 1: feat=g_feat (stride 1024), out=g_cat, epilogue = lrelu(o + bh[h])
//   LAYER 2: feat=g_h2  (stride 64),   out=d_out, epilogue = lrelu(o + b_out)
// Block: 64 query rows, 256 threads (16x16). Per-thread: 4 rows, D/16 out cols.
// ---------------------------------------------------------------------------
template <int D, int LAYER>
__global__ __launch_bounds__(256, 2) void attn_kernel(const float* __restrict__ graph,
                                                      const float* __restrict__ bias,
                                                      float* __restrict__ out2) {
    constexpr int LD  = D + 4;   // float4-aligned (mod 4 == 0), col-stride mod 32 == 4
    constexpr int PLD = 68;
    constexpr int CPT = D / 16;  // cols per thread (8 or 4)
    extern __shared__ float smem[];
    float* sQ = smem;
    float* sK = smem + 64 * LD;
    float* sP = sK + 64 * LD;

    const int tid = threadIdx.x;
    const int tx = tid & 15, ty = tid >> 4;
    const int n0 = blockIdx.x * 64;
    const int b  = blockIdx.y;
    const int h  = blockIdx.z;

    const int fstride = (LAYER == 1) ? CAT_ : COUT_;
    const float* feat = (LAYER == 1) ? g_feat : g_h2;
    float* outp       = (LAYER == 1) ? g_cat : out2;
    const float* Qb = feat + (size_t)b * N_ * fstride + h * D;
    float* Ob       = outp + (size_t)b * N_ * fstride + h * D;
    const float* bias_h = bias + h * D;

    // Q tile -> smem
    for (int i = tid; i < 64 * D; i += 256) {
        int r = i / D, c = i - r * D;
        sQ[r * LD + c] = Qb[(size_t)(n0 + r) * fstride + c];
    }

    float o[4][CPT];
#pragma unroll
    for (int i = 0; i < 4; i++)
#pragma unroll
        for (int c = 0; c < CPT; c++) o[i][c] = 0.f;
    float mrow[4] = {-INFINITY, -INFINITY, -INFINITY, -INFINITY};
    float lrow[4] = {0.f, 0.f, 0.f, 0.f};

    __syncthreads();

    for (int m0 = 0; m0 < N_; m0 += 64) {
        // K/V tile -> smem
        for (int i = tid; i < 64 * D; i += 256) {
            int r = i / D, c = i - r * D;
            sK[r * LD + c] = Qb[(size_t)(m0 + r) * fstride + c];
        }
        __syncthreads();

        // adjacency mask (graph is 4MB, L2-resident; overlaps with score compute)
        float g[4][4];
#pragma unroll
        for (int i = 0; i < 4; i++)
#pragma unroll
            for (int j = 0; j < 4; j++)
                g[i][j] = __ldg(&graph[(size_t)(n0 + ty * 4 + i) * N_ + m0 + tx + 16 * j]);

        // S = Q K^T  (4x4 per thread, cols = tx + 16*j : conflict-free)
        float s[4][4];
#pragma unroll
        for (int i = 0; i < 4; i++)
#pragma unroll
            for (int j = 0; j < 4; j++) s[i][j] = 0.f;

#pragma unroll 4
        for (int d0 = 0; d0 < D; d0 += 4) {
            float4 qv[4], kv[4];
#pragma unroll
            for (int i = 0; i < 4; i++)
                qv[i] = *(const float4*)(sQ + (ty * 4 + i) * LD + d0);
#pragma unroll
            for (int j = 0; j < 4; j++)
                kv[j] = *(const float4*)(sK + (tx + 16 * j) * LD + d0);
#pragma unroll
            for (int i = 0; i < 4; i++)
#pragma unroll
                for (int j = 0; j < 4; j++) {
                    s[i][j] = fmaf(qv[i].x, kv[j].x, s[i][j]);
                    s[i][j] = fmaf(qv[i].y, kv[j].y, s[i][j]);
                    s[i][j] = fmaf(qv[i].z, kv[j].z, s[i][j]);
                    s[i][j] = fmaf(qv[i].w, kv[j].w, s[i][j]);
                }
        }

        // mask: graph==0 -> -1e16 (matches torch/jax masked_fill semantics)
#pragma unroll
        for (int i = 0; i < 4; i++)
#pragma unroll
            for (int j = 0; j < 4; j++)
                s[i][j] = (g[i][j] != 0.f) ? s[i][j] : -1e16f;

        // online softmax per row (row shared by 16 lanes of same ty; aligned in warp)
#pragma unroll
        for (int i = 0; i < 4; i++) {
            float tm = fmaxf(fmaxf(s[i][0], s[i][1]), fmaxf(s[i][2], s[i][3]));
#pragma unroll
            for (int off = 8; off >= 1; off >>= 1)
                tm = fmaxf(tm, __shfl_xor_sync(0xffffffffu, tm, off));
            float nm = fmaxf(mrow[i], tm);
            float scale = __expf(mrow[i] - nm);
            float ls = 0.f;
#pragma unroll
            for (int j = 0; j < 4; j++) {
                s[i][j] = __expf(s[i][j] - nm);
                ls += s[i][j];
            }
#pragma unroll
            for (int off = 8; off >= 1; off >>= 1)
                ls += __shfl_xor_sync(0xffffffffu, ls, off);
            lrow[i] = lrow[i] * scale + ls;
            mrow[i] = nm;
#pragma unroll
            for (int c = 0; c < CPT; c++) o[i][c] *= scale;
#pragma unroll
            for (int j = 0; j < 4; j++) sP[(ty * 4 + i) * PLD + tx + 16 * j] = s[i][j];
        }
        __syncthreads();

        // O += P @ V  (V tile == K tile; cols = tx + 16*c : conflict-free)
#pragma unroll 4
        for (int m4 = 0; m4 < 64; m4 += 4) {
            float4 pv[4];
#pragma unroll
            for (int i = 0; i < 4; i++)
                pv[i] = *(const float4*)(sP + (ty * 4 + i) * PLD + m4);
            float pa[4][4];
#pragma unroll
            for (int i = 0; i < 4; i++) {
                pa[i][0] = pv[i].x; pa[i][1] = pv[i].y;
                pa[i][2] = pv[i].z; pa[i][3] = pv[i].w;
            }
#pragma unroll
            for (int mm = 0; mm < 4; mm++) {
#pragma unroll
                for (int c = 0; c < CPT; c++) {
                    float kv = sK[(m4 + mm) * LD + tx + 16 * c];
#pragma unroll
                    for (int i = 0; i < 4; i++)
                        o[i][c] = fmaf(pa[i][mm], kv, o[i][c]);
                }
            }
        }
        __syncthreads();
    }

    // epilogue: normalize, bias, leaky_relu(0.01)
#pragma unroll
    for (int i = 0; i < 4; i++) {
        float inv = 1.f / lrow[i];
#pragma unroll
        for (int c = 0; c < CPT; c++) {
            float v = fmaf(o[i][c] * inv, 1.f, bias_h[tx + 16 * c]);
            v = (v > 0.f) ? v : 0.01f * v;
            Ob[(size_t)(n0 + ty * 4 + i) * fstride + tx + 16 * c] = v;
        }
    }
}

// ---------------------------------------------------------------------------
// Kernel 3: g_h2 = g_cat(activated) @ W_out   (M=16384, K=1024, Nc=64)
// ---------------------------------------------------------------------------
__global__ __launch_bounds__(256) void gemm2_kernel(const float* __restrict__ Wout) {
    __shared__ float sA[64][68];
    __shared__ float sB[64][68];
    const int tid = threadIdx.x;
    const int tx = tid & 15, ty = tid >> 4;
    const int bn0 = blockIdx.x * 64;

    float acc[4][4];
#pragma unroll
    for (int i = 0; i < 4; i++)
#pragma unroll
        for (int j = 0; j < 4; j++) acc[i][j] = 0.f;

    for (int k0 = 0; k0 < CAT_; k0 += 64) {
        for (int i = tid; i < 64 * 64; i += 256) {
            int r = i >> 6, c = i & 63;
            sA[r][c] = g_cat[(size_t)(bn0 + r) * CAT_ + k0 + c];
            sB[r][c] = Wout[(size_t)(k0 + r) * COUT_ + c];
        }
        __syncthreads();
#pragma unroll 4
        for (int k = 0; k < 64; k++) {
            float av[4], bv[4];
#pragma unroll
            for (int i = 0; i < 4; i++) av[i] = sA[ty * 4 + i][k];
#pragma unroll
            for (int j = 0; j < 4; j++) bv[j] = sB[k][tx + 16 * j];
#pragma unroll
            for (int i = 0; i < 4; i++)
#pragma unroll
                for (int j = 0; j < 4; j++) acc[i][j] = fmaf(av[i], bv[j], acc[i][j]);
        }
        __syncthreads();
    }

#pragma unroll
    for (int i = 0; i < 4; i++)
#pragma unroll
        for (int j = 0; j < 4; j++)
            g_h2[(size_t)(bn0 + ty * 4 + i) * COUT_ + tx + 16 * j] = acc[i][j];
}

// ---------------------------------------------------------------------------
extern "C" void kernel_launch(void* const* d_in, const int* in_sizes, int n_in,
                              void* d_out, int out_size) {
    const float* flow_x = (const float*)d_in[0];
    const float* graph  = (const float*)d_in[1];
    const float* Wh     = (const float*)d_in[2];
    const float* bh     = (const float*)d_in[3];
    const float* W_out  = (const float*)d_in[4];
    const float* b_out  = (const float*)d_in[5];
    float* out = (float*)d_out;

    constexpr int SMEM128 = (64 * (128 + 4) * 2 + 64 * 68) * 4;  // 84992 B
    constexpr int SMEM64  = (64 * (64 + 4) * 2 + 64 * 68) * 4;   // 52224 B
    cudaFuncSetAttribute(attn_kernel<128, 1>, cudaFuncAttributeMaxDynamicSharedMemorySize, SMEM128);
    cudaFuncSetAttribute(attn_kernel<64, 2>,  cudaFuncAttributeMaxDynamicSharedMemorySize, SMEM64);

    gemm1_kernel<<<dim3(B_ * N_ / 64, H_), 256>>>(flow_x, Wh);
    attn_kernel<128, 1><<<dim3(N_ / 64, B_, H_), 256, SMEM128>>>(graph, bh, nullptr);
    gemm2_kernel<<<dim3(B_ * N_ / 64), 256>>>(W_out);
    attn_kernel<64, 2><<<dim3(N_ / 64, B_, 1), 256, SMEM64>>>(graph, b_out, out);
}

// round 3
// speedup vs baseline: 1.1400x; 1.1400x over previous
#include <cuda_runtime.h>
#include <math.h>

// Problem constants
constexpr int B_   = 16;
constexpr int N_   = 1024;
constexpr int CIN_ = 64;
constexpr int HID_ = 128;
constexpr int H_   = 8;
constexpr int COUT_= 64;
constexpr int CAT_ = HID_ * H_;   // 1024

typedef unsigned long long ull;

// Scratch (device globals — no allocation allowed)
__device__ float g_feat[B_ * N_ * CAT_];   // layer-1 per-head features, concat layout
__device__ float g_cat [B_ * N_ * CAT_];   // leakyrelu(attn1 + bh) in concat layout
__device__ float g_h2  [B_ * N_ * COUT_];  // layer-2 features

// ---- packed f32x2 helpers (sm_103a FFMA2: 2 fp32 FMAs per issued instr) ----
__device__ __forceinline__ ull f2pack(float lo, float hi) {
    ull r; asm("mov.b64 %0, {%1, %2};" : "=l"(r) : "f"(lo), "f"(hi)); return r;
}
__device__ __forceinline__ float2 f2unpack(ull v) {
    float2 r; asm("mov.b64 {%0, %1}, %2;" : "=f"(r.x), "=f"(r.y) : "l"(v)); return r;
}
__device__ __forceinline__ ull ffma2(ull a, ull b, ull c) {
    ull d; asm("fma.rn.f32x2 %0, %1, %2, %3;" : "=l"(d) : "l"(a), "l"(b), "l"(c)); return d;
}
__device__ __forceinline__ ull fmul2(ull a, ull b) {
    ull d; asm("mul.rn.f32x2 %0, %1, %2;" : "=l"(d) : "l"(a), "l"(b)); return d;
}

// ---------------------------------------------------------------------------
// Kernel 1: g_feat[bn][h*128 + c] = flow_x[bn] @ Wh[h]   (M=16384, K=64, Nc=128)
// Thread owns 4 rows (ty*4+i), cols 64g + 4tx + {0..3}, g<2. f32x2 inner.
// ---------------------------------------------------------------------------
__global__ __launch_bounds__(256) void gemm1_kernel(const float* __restrict__ x,
                                                    const float* __restrict__ Wh) {
    __shared__ float sX[64 * CIN_];    // 16 KB, stride 64
    __shared__ float sW[CIN_ * HID_];  // 32 KB, stride 128
    const int tid = threadIdx.x;
    const int tx = tid & 15, ty = tid >> 4;
    const int bn0 = blockIdx.x * 64;
    const int h = blockIdx.y;
    const float* Wp = Wh + (size_t)h * CIN_ * HID_;

    for (int i = tid; i < CIN_ * HID_ / 4; i += 256)
        *(float4*)(sW + i * 4) = *(const float4*)(Wp + i * 4);
    for (int i = tid; i < 64 * CIN_ / 4; i += 256) {
        int r = i >> 4, c4 = i & 15;
        *(float4*)(sX + r * CIN_ + c4 * 4) =
            *(const float4*)(x + (size_t)(bn0 + r) * CIN_ + c4 * 4);
    }
    __syncthreads();

    ull acc2[4][4];   // [row][g*2+p]
#pragma unroll
    for (int i = 0; i < 4; i++)
#pragma unroll
        for (int j = 0; j < 4; j++) acc2[i][j] = 0ull;

#pragma unroll 4
    for (int k4 = 0; k4 < CIN_; k4 += 4) {
        float4 av[4];
#pragma unroll
        for (int i = 0; i < 4; i++)
            av[i] = *(const float4*)(sX + (ty * 4 + i) * CIN_ + k4);
#pragma unroll
        for (int k = 0; k < 4; k++) {
            ulonglong2 wv[2];
#pragma unroll
            for (int g = 0; g < 2; g++)
                wv[g] = *(const ulonglong2*)(sW + (k4 + k) * HID_ + 64 * g + 4 * tx);
#pragma unroll
            for (int i = 0; i < 4; i++) {
                float a = ((const float*)&av[i])[k];
                ull pp = f2pack(a, a);
#pragma unroll
                for (int g = 0; g < 2; g++) {
                    acc2[i][g * 2 + 0] = ffma2(pp, wv[g].x, acc2[i][g * 2 + 0]);
                    acc2[i][g * 2 + 1] = ffma2(pp, wv[g].y, acc2[i][g * 2 + 1]);
                }
            }
        }
    }

#pragma unroll
    for (int i = 0; i < 4; i++)
#pragma unroll
        for (int g = 0; g < 2; g++) {
            float2 e0 = f2unpack(acc2[i][g * 2 + 0]);
            float2 e1 = f2unpack(acc2[i][g * 2 + 1]);
            float4 v = make_float4(e0.x, e0.y, e1.x, e1.y);
            *(float4*)(g_feat + (size_t)(bn0 + ty * 4 + i) * CAT_ + h * HID_ + 64 * g + 4 * tx) = v;
        }
}

// ---------------------------------------------------------------------------
// Fused masked-softmax attention (flash-style), Q=K=V=feat, f32x2 math.
//   LAYER 1: feat=g_feat (stride 1024), out=g_cat, epilogue = lrelu(o + bh[h])
//   LAYER 2: feat=g_h2  (stride 64),   out=d_out, epilogue = lrelu(o + b_out)
// Block: 64 query rows, 256 threads (16x16). S tile 4x4/thread (cols tx+16j),
// O cols owned as contiguous 4-blocks: 64g + 4tx + {0..3}.
// ---------------------------------------------------------------------------
template <int D, int LAYER>
__global__ __launch_bounds__(256, 2) void attn_kernel(const float* __restrict__ graph,
                                                      const float* __restrict__ bias,
                                                      float* __restrict__ out2) {
    constexpr int LD  = D + 4;   // float4-aligned
    constexpr int PLD = 68;
    constexpr int G   = D / 64;  // output col groups per thread (2 or 1)
    extern __shared__ float smem[];
    float* sQ = smem;
    float* sK = smem + 64 * LD;
    float* sP = sK + 64 * LD;

    const int tid = threadIdx.x;
    const int tx = tid & 15, ty = tid >> 4;
    const int n0 = blockIdx.x * 64;
    const int b  = blockIdx.y;
    const int h  = blockIdx.z;

    const int fstride = (LAYER == 1) ? CAT_ : COUT_;
    const float* feat = (LAYER == 1) ? g_feat : g_h2;
    float* outp       = (LAYER == 1) ? g_cat : out2;
    const float* Qb = feat + (size_t)b * N_ * fstride + h * D;
    float* Ob       = outp + (size_t)b * N_ * fstride + h * D;
    const float* bias_h = bias + h * D;

    // Q tile -> smem (vectorized)
    for (int i = tid; i < 64 * D / 4; i += 256) {
        int r = i / (D / 4), c4 = i % (D / 4);
        *(float4*)(sQ + r * LD + c4 * 4) =
            *(const float4*)(Qb + (size_t)(n0 + r) * fstride + c4 * 4);
    }

    ull o2[4][2 * G];
#pragma unroll
    for (int i = 0; i < 4; i++)
#pragma unroll
        for (int c = 0; c < 2 * G; c++) o2[i][c] = 0ull;
    float mrow[4] = {-INFINITY, -INFINITY, -INFINITY, -INFINITY};
    float lrow[4] = {0.f, 0.f, 0.f, 0.f};

    __syncthreads();

    for (int m0 = 0; m0 < N_; m0 += 64) {
        // K/V tile -> smem (vectorized)
        for (int i = tid; i < 64 * D / 4; i += 256) {
            int r = i / (D / 4), c4 = i % (D / 4);
            *(float4*)(sK + r * LD + c4 * 4) =
                *(const float4*)(Qb + (size_t)(m0 + r) * fstride + c4 * 4);
        }
        __syncthreads();

        // adjacency mask (L2-resident; overlaps with score compute)
        float g[4][4];
#pragma unroll
        for (int i = 0; i < 4; i++)
#pragma unroll
            for (int j = 0; j < 4; j++)
                g[i][j] = __ldg(&graph[(size_t)(n0 + ty * 4 + i) * N_ + m0 + tx + 16 * j]);

        // S = Q K^T, packed over d: acc holds (even-d, odd-d) partial sums
        ull acc2[4][4];
#pragma unroll
        for (int i = 0; i < 4; i++)
#pragma unroll
            for (int j = 0; j < 4; j++) acc2[i][j] = 0ull;

#pragma unroll 4
        for (int d0 = 0; d0 < D; d0 += 4) {
            ulonglong2 q2[4], k2[4];
#pragma unroll
            for (int i = 0; i < 4; i++)
                q2[i] = *(const ulonglong2*)(sQ + (ty * 4 + i) * LD + d0);
#pragma unroll
            for (int j = 0; j < 4; j++)
                k2[j] = *(const ulonglong2*)(sK + (tx + 16 * j) * LD + d0);
#pragma unroll
            for (int i = 0; i < 4; i++)
#pragma unroll
                for (int j = 0; j < 4; j++) {
                    acc2[i][j] = ffma2(q2[i].x, k2[j].x, acc2[i][j]);
                    acc2[i][j] = ffma2(q2[i].y, k2[j].y, acc2[i][j]);
                }
        }

        float s[4][4];
#pragma unroll
        for (int i = 0; i < 4; i++)
#pragma unroll
            for (int j = 0; j < 4; j++) {
                float2 e = f2unpack(acc2[i][j]);
                float v = e.x + e.y;
                s[i][j] = (g[i][j] != 0.f) ? v : -1e16f;
            }

        // online softmax per row (16 lanes share a row, contiguous in warp)
#pragma unroll
        for (int i = 0; i < 4; i++) {
            float tm = fmaxf(fmaxf(s[i][0], s[i][1]), fmaxf(s[i][2], s[i][3]));
#pragma unroll
            for (int off = 8; off >= 1; off >>= 1)
                tm = fmaxf(tm, __shfl_xor_sync(0xffffffffu, tm, off));
            float nm = fmaxf(mrow[i], tm);
            float scale = __expf(mrow[i] - nm);
            float ls = 0.f;
#pragma unroll
            for (int j = 0; j < 4; j++) {
                s[i][j] = __expf(s[i][j] - nm);
                ls += s[i][j];
            }
#pragma unroll
            for (int off = 8; off >= 1; off >>= 1)
                ls += __shfl_xor_sync(0xffffffffu, ls, off);
            lrow[i] = lrow[i] * scale + ls;
            mrow[i] = nm;
            ull sc2 = f2pack(scale, scale);
#pragma unroll
            for (int c = 0; c < 2 * G; c++) o2[i][c] = fmul2(o2[i][c], sc2);
#pragma unroll
            for (int j = 0; j < 4; j++) sP[(ty * 4 + i) * PLD + tx + 16 * j] = s[i][j];
        }
        __syncthreads();

        // O += P @ V  (V tile == K tile; cols 64g + 4tx, vector loads)
#pragma unroll 4
        for (int m4 = 0; m4 < 64; m4 += 4) {
            float4 pa[4];
#pragma unroll
            for (int i = 0; i < 4; i++)
                pa[i] = *(const float4*)(sP + (ty * 4 + i) * PLD + m4);
#pragma unroll
            for (int mm = 0; mm < 4; mm++) {
                ulonglong2 vv[G];
#pragma unroll
                for (int gg = 0; gg < G; gg++)
                    vv[gg] = *(const ulonglong2*)(sK + (m4 + mm) * LD + 64 * gg + 4 * tx);
#pragma unroll
                for (int i = 0; i < 4; i++) {
                    float p = ((const float*)&pa[i])[mm];
                    ull pp = f2pack(p, p);
#pragma unroll
                    for (int gg = 0; gg < G; gg++) {
                        o2[i][gg * 2 + 0] = ffma2(pp, vv[gg].x, o2[i][gg * 2 + 0]);
                        o2[i][gg * 2 + 1] = ffma2(pp, vv[gg].y, o2[i][gg * 2 + 1]);
                    }
                }
            }
        }
        __syncthreads();
    }

    // epilogue: normalize, bias, leaky_relu(0.01), vectorized store
#pragma unroll
    for (int i = 0; i < 4; i++) {
        float inv = 1.f / lrow[i];
#pragma unroll
        for (int gg = 0; gg < G; gg++) {
            float4 bv = *(const float4*)(bias_h + 64 * gg + 4 * tx);
            float2 e0 = f2unpack(o2[i][gg * 2 + 0]);
            float2 e1 = f2unpack(o2[i][gg * 2 + 1]);
            float v0 = fmaf(e0.x, inv, bv.x);
            float v1 = fmaf(e0.y, inv, bv.y);
            float v2 = fmaf(e1.x, inv, bv.z);
            float v3 = fmaf(e1.y, inv, bv.w);
            v0 = (v0 > 0.f) ? v0 : 0.01f * v0;
            v1 = (v1 > 0.f) ? v1 : 0.01f * v1;
            v2 = (v2 > 0.f) ? v2 : 0.01f * v2;
            v3 = (v3 > 0.f) ? v3 : 0.01f * v3;
            *(float4*)(Ob + (size_t)(n0 + ty * 4 + i) * fstride + 64 * gg + 4 * tx) =
                make_float4(v0, v1, v2, v3);
        }
    }
}

// ---------------------------------------------------------------------------
// Kernel 3: g_h2 = g_cat @ W_out   (M=16384, K=1024, Nc=64)
// Tile 128 rows x 64 cols; thread: 8 rows (ty*8+i) x 4 cols (4tx+q). f32x2.
// ---------------------------------------------------------------------------
__global__ __launch_bounds__(256) void gemm2_kernel(const float* __restrict__ Wout) {
    __shared__ float sA[128 * 64];  // 32 KB, stride 64
    __shared__ float sB[64 * 64];   // 16 KB, stride 64
    const int tid = threadIdx.x;
    const int tx = tid & 15, ty = tid >> 4;
    const int bn0 = blockIdx.x * 128;

    ull acc2[8][2];
#pragma unroll
    for (int i = 0; i < 8; i++) { acc2[i][0] = 0ull; acc2[i][1] = 0ull; }

    for (int k0 = 0; k0 < CAT_; k0 += 64) {
        for (int i = tid; i < 128 * 16; i += 256) {
            int r = i >> 4, c4 = i & 15;
            *(float4*)(sA + r * 64 + c4 * 4) =
                *(const float4*)(g_cat + (size_t)(bn0 + r) * CAT_ + k0 + c4 * 4);
        }
        for (int i = tid; i < 64 * 16; i += 256) {
            int r = i >> 4, c4 = i & 15;
            *(float4*)(sB + r * 64 + c4 * 4) =
                *(const float4*)(Wout + (size_t)(k0 + r) * COUT_ + c4 * 4);
        }
        __syncthreads();
#pragma unroll 2
        for (int k4 = 0; k4 < 64; k4 += 4) {
            float4 av[8];
#pragma unroll
            for (int i = 0; i < 8; i++)
                av[i] = *(const float4*)(sA + (ty * 8 + i) * 64 + k4);
#pragma unroll
            for (int k = 0; k < 4; k++) {
                ulonglong2 bv = *(const ulonglong2*)(sB + (k4 + k) * 64 + 4 * tx);
#pragma unroll
                for (int i = 0; i < 8; i++) {
                    float a = ((const float*)&av[i])[k];
                    ull pp = f2pack(a, a);
                    acc2[i][0] = ffma2(pp, bv.x, acc2[i][0]);
                    acc2[i][1] = ffma2(pp, bv.y, acc2[i][1]);
                }
            }
        }
        __syncthreads();
    }

#pragma unroll
    for (int i = 0; i < 8; i++) {
        float2 e0 = f2unpack(acc2[i][0]);
        float2 e1 = f2unpack(acc2[i][1]);
        *(float4*)(g_h2 + (size_t)(bn0 + ty * 8 + i) * COUT_ + 4 * tx) =
            make_float4(e0.x, e0.y, e1.x, e1.y);
    }
}

// ---------------------------------------------------------------------------
extern "C" void kernel_launch(void* const* d_in, const int* in_sizes, int n_in,
                              void* d_out, int out_size) {
    const float* flow_x = (const float*)d_in[0];
    const float* graph  = (const float*)d_in[1];
    const float* Wh     = (const float*)d_in[2];
    const float* bh     = (const float*)d_in[3];
    const float* W_out  = (const float*)d_in[4];
    const float* b_out  = (const float*)d_in[5];
    float* out = (float*)d_out;

    constexpr int SMEM128 = (64 * (128 + 4) * 2 + 64 * 68) * 4;  // 84992 B
    constexpr int SMEM64  = (64 * (64 + 4) * 2 + 64 * 68) * 4;   // 52224 B
    cudaFuncSetAttribute(attn_kernel<128, 1>, cudaFuncAttributeMaxDynamicSharedMemorySize, SMEM128);
    cudaFuncSetAttribute(attn_kernel<64, 2>,  cudaFuncAttributeMaxDynamicSharedMemorySize, SMEM64);

    gemm1_kernel<<<dim3(B_ * N_ / 64, H_), 256>>>(flow_x, Wh);
    attn_kernel<128, 1><<<dim3(N_ / 64, B_, H_), 256, SMEM128>>>(graph, bh, nullptr);
    gemm2_kernel<<<dim3(B_ * N_ / 128), 256>>>(W_out);
    attn_kernel<64, 2><<<dim3(N_ / 64, B_, 1), 256, SMEM64>>>(graph, b_out, out);
}

// round 4
// speedup vs baseline: 1.1405x; 1.0004x over previous
#include <cuda_runtime.h>
#include <math.h>

// Problem constants
constexpr int B_   = 16;
constexpr int N_   = 1024;
constexpr int CIN_ = 64;
constexpr int HID_ = 128;
constexpr int H_   = 8;
constexpr int COUT_= 64;
constexpr int CAT_ = HID_ * H_;   // 1024

typedef unsigned long long ull;

// Scratch (device globals — no allocation allowed)
__device__ float g_feat[B_ * N_ * CAT_];   // layer-1 per-head features, concat layout
__device__ float g_cat [B_ * N_ * CAT_];   // leakyrelu(attn1 + bh) in concat layout
__device__ float g_h2  [B_ * N_ * COUT_];  // layer-2 features

// ---- packed f32x2 helpers (sm_103a FFMA2: 2 fp32 FMAs per issued instr) ----
__device__ __forceinline__ ull f2pack(float lo, float hi) {
    ull r; asm("mov.b64 %0, {%1, %2};" : "=l"(r) : "f"(lo), "f"(hi)); return r;
}
__device__ __forceinline__ float2 f2unpack(ull v) {
    float2 r; asm("mov.b64 {%0, %1}, %2;" : "=f"(r.x), "=f"(r.y) : "l"(v)); return r;
}
__device__ __forceinline__ ull ffma2(ull a, ull b, ull c) {
    ull d; asm("fma.rn.f32x2 %0, %1, %2, %3;" : "=l"(d) : "l"(a), "l"(b), "l"(c)); return d;
}
__device__ __forceinline__ ull fmul2(ull a, ull b) {
    ull d; asm("mul.rn.f32x2 %0, %1, %2;" : "=l"(d) : "l"(a), "l"(b)); return d;
}

// ---------------------------------------------------------------------------
// Kernel 1: g_feat[bn][h*128 + c] = flow_x[bn] @ Wh[h]   (M=16384, K=64, Nc=128)
// Thread owns 4 rows (ty*4+i), cols 64g + 4tx + {0..3}, g<2. f32x2 inner.
// ---------------------------------------------------------------------------
__global__ __launch_bounds__(256) void gemm1_kernel(const float* __restrict__ x,
                                                    const float* __restrict__ Wh) {
    __shared__ float sX[64 * CIN_];    // 16 KB, stride 64
    __shared__ float sW[CIN_ * HID_];  // 32 KB, stride 128
    const int tid = threadIdx.x;
    const int tx = tid & 15, ty = tid >> 4;
    const int bn0 = blockIdx.x * 64;
    const int h = blockIdx.y;
    const float* Wp = Wh + (size_t)h * CIN_ * HID_;

    for (int i = tid; i < CIN_ * HID_ / 4; i += 256)
        *(float4*)(sW + i * 4) = *(const float4*)(Wp + i * 4);
    for (int i = tid; i < 64 * CIN_ / 4; i += 256) {
        int r = i >> 4, c4 = i & 15;
        *(float4*)(sX + r * CIN_ + c4 * 4) =
            *(const float4*)(x + (size_t)(bn0 + r) * CIN_ + c4 * 4);
    }
    __syncthreads();

    ull acc2[4][4];   // [row][g*2+p]
#pragma unroll
    for (int i = 0; i < 4; i++)
#pragma unroll
        for (int j = 0; j < 4; j++) acc2[i][j] = 0ull;

#pragma unroll 4
    for (int k4 = 0; k4 < CIN_; k4 += 4) {
        float4 av[4];
#pragma unroll
        for (int i = 0; i < 4; i++)
            av[i] = *(const float4*)(sX + (ty * 4 + i) * CIN_ + k4);
#pragma unroll
        for (int k = 0; k < 4; k++) {
            ulonglong2 wv[2];
#pragma unroll
            for (int g = 0; g < 2; g++)
                wv[g] = *(const ulonglong2*)(sW + (k4 + k) * HID_ + 64 * g + 4 * tx);
#pragma unroll
            for (int i = 0; i < 4; i++) {
                float a = ((const float*)&av[i])[k];
                ull pp = f2pack(a, a);
#pragma unroll
                for (int g = 0; g < 2; g++) {
                    acc2[i][g * 2 + 0] = ffma2(pp, wv[g].x, acc2[i][g * 2 + 0]);
                    acc2[i][g * 2 + 1] = ffma2(pp, wv[g].y, acc2[i][g * 2 + 1]);
                }
            }
        }
    }

#pragma unroll
    for (int i = 0; i < 4; i++)
#pragma unroll
        for (int g = 0; g < 2; g++) {
            float2 e0 = f2unpack(acc2[i][g * 2 + 0]);
            float2 e1 = f2unpack(acc2[i][g * 2 + 1]);
            float4 v = make_float4(e0.x, e0.y, e1.x, e1.y);
            *(float4*)(g_feat + (size_t)(bn0 + ty * 4 + i) * CAT_ + h * HID_ + 64 * g + 4 * tx) = v;
        }
}

// ---------------------------------------------------------------------------
// Fused masked-softmax attention (flash-style), Q=K=V=feat, f32x2 math.
//   LAYER 1: feat=g_feat (stride 1024), out=g_cat, epilogue = lrelu(o + bh[h])
//   LAYER 2: feat=g_h2  (stride 64),   out=d_out, epilogue = lrelu(o + b_out)
// Block: 64 query rows, 256 threads (16x16). S tile 4x4/thread (cols tx+16j),
// O cols owned as contiguous 4-blocks: 64g + 4tx + {0..3}.
// ---------------------------------------------------------------------------
template <int D, int LAYER>
__global__ __launch_bounds__(256, 2) void attn_kernel(const float* __restrict__ graph,
                                                      const float* __restrict__ bias,
                                                      float* __restrict__ out2) {
    constexpr int LD  = D + 4;   // float4-aligned
    constexpr int PLD = 68;
    constexpr int G   = D / 64;  // output col groups per thread (2 or 1)
    extern __shared__ float smem[];
    float* sQ = smem;
    float* sK = smem + 64 * LD;
    float* sP = sK + 64 * LD;

    const int tid = threadIdx.x;
    const int tx = tid & 15, ty = tid >> 4;
    const int n0 = blockIdx.x * 64;
    const int b  = blockIdx.y;
    const int h  = blockIdx.z;

    const int fstride = (LAYER == 1) ? CAT_ : COUT_;
    const float* feat = (LAYER == 1) ? g_feat : g_h2;
    float* outp       = (LAYER == 1) ? g_cat : out2;
    const float* Qb = feat + (size_t)b * N_ * fstride + h * D;
    float* Ob       = outp + (size_t)b * N_ * fstride + h * D;
    const float* bias_h = bias + h * D;

    // Q tile -> smem (vectorized)
    for (int i = tid; i < 64 * D / 4; i += 256) {
        int r = i / (D / 4), c4 = i % (D / 4);
        *(float4*)(sQ + r * LD + c4 * 4) =
            *(const float4*)(Qb + (size_t)(n0 + r) * fstride + c4 * 4);
    }

    ull o2[4][2 * G];
#pragma unroll
    for (int i = 0; i < 4; i++)
#pragma unroll
        for (int c = 0; c < 2 * G; c++) o2[i][c] = 0ull;
    float mrow[4] = {-INFINITY, -INFINITY, -INFINITY, -INFINITY};
    float lrow[4] = {0.f, 0.f, 0.f, 0.f};

    __syncthreads();

    for (int m0 = 0; m0 < N_; m0 += 64) {
        // K/V tile -> smem (vectorized)
        for (int i = tid; i < 64 * D / 4; i += 256) {
            int r = i / (D / 4), c4 = i % (D / 4);
            *(float4*)(sK + r * LD + c4 * 4) =
                *(const float4*)(Qb + (size_t)(m0 + r) * fstride + c4 * 4);
        }
        __syncthreads();

        // adjacency mask (L2-resident; overlaps with score compute)
        float g[4][4];
#pragma unroll
        for (int i = 0; i < 4; i++)
#pragma unroll
            for (int j = 0; j < 4; j++)
                g[i][j] = __ldg(&graph[(size_t)(n0 + ty * 4 + i) * N_ + m0 + tx + 16 * j]);

        // S = Q K^T, packed over d: acc holds (even-d, odd-d) partial sums
        ull acc2[4][4];
#pragma unroll
        for (int i = 0; i < 4; i++)
#pragma unroll
            for (int j = 0; j < 4; j++) acc2[i][j] = 0ull;

#pragma unroll 4
        for (int d0 = 0; d0 < D; d0 += 4) {
            ulonglong2 q2[4], k2[4];
#pragma unroll
            for (int i = 0; i < 4; i++)
                q2[i] = *(const ulonglong2*)(sQ + (ty * 4 + i) * LD + d0);
#pragma unroll
            for (int j = 0; j < 4; j++)
                k2[j] = *(const ulonglong2*)(sK + (tx + 16 * j) * LD + d0);
#pragma unroll
            for (int i = 0; i < 4; i++)
#pragma unroll
                for (int j = 0; j < 4; j++) {
                    acc2[i][j] = ffma2(q2[i].x, k2[j].x, acc2[i][j]);
                    acc2[i][j] = ffma2(q2[i].y, k2[j].y, acc2[i][j]);
                }
        }

        float s[4][4];
#pragma unroll
        for (int i = 0; i < 4; i++)
#pragma unroll
            for (int j = 0; j < 4; j++) {
                float2 e = f2unpack(acc2[i][j]);
                float v = e.x + e.y;
                s[i][j] = (g[i][j] != 0.f) ? v : -1e16f;
            }

        // online softmax per row (16 lanes share a row, contiguous in warp)
#pragma unroll
        for (int i = 0; i < 4; i++) {
            float tm = fmaxf(fmaxf(s[i][0], s[i][1]), fmaxf(s[i][2], s[i][3]));
#pragma unroll
            for (int off = 8; off >= 1; off >>= 1)
                tm = fmaxf(tm, __shfl_xor_sync(0xffffffffu, tm, off));
            float nm = fmaxf(mrow[i], tm);
            float scale = __expf(mrow[i] - nm);
            float ls = 0.f;
#pragma unroll
            for (int j = 0; j < 4; j++) {
                s[i][j] = __expf(s[i][j] - nm);
                ls += s[i][j];
            }
#pragma unroll
            for (int off = 8; off >= 1; off >>= 1)
                ls += __shfl_xor_sync(0xffffffffu, ls, off);
            lrow[i] = lrow[i] * scale + ls;
            mrow[i] = nm;
            ull sc2 = f2pack(scale, scale);
#pragma unroll
            for (int c = 0; c < 2 * G; c++) o2[i][c] = fmul2(o2[i][c], sc2);
#pragma unroll
            for (int j = 0; j < 4; j++) sP[(ty * 4 + i) * PLD + tx + 16 * j] = s[i][j];
        }
        __syncthreads();

        // O += P @ V  (V tile == K tile; cols 64g + 4tx, vector loads)
#pragma unroll 4
        for (int m4 = 0; m4 < 64; m4 += 4) {
            float4 pa[4];
#pragma unroll
            for (int i = 0; i < 4; i++)
                pa[i] = *(const float4*)(sP + (ty * 4 + i) * PLD + m4);
#pragma unroll
            for (int mm = 0; mm < 4; mm++) {
                ulonglong2 vv[G];
#pragma unroll
                for (int gg = 0; gg < G; gg++)
                    vv[gg] = *(const ulonglong2*)(sK + (m4 + mm) * LD + 64 * gg + 4 * tx);
#pragma unroll
                for (int i = 0; i < 4; i++) {
                    float p = ((const float*)&pa[i])[mm];
                    ull pp = f2pack(p, p);
#pragma unroll
                    for (int gg = 0; gg < G; gg++) {
                        o2[i][gg * 2 + 0] = ffma2(pp, vv[gg].x, o2[i][gg * 2 + 0]);
                        o2[i][gg * 2 + 1] = ffma2(pp, vv[gg].y, o2[i][gg * 2 + 1]);
                    }
                }
            }
        }
        __syncthreads();
    }

    // epilogue: normalize, bias, leaky_relu(0.01), vectorized store
#pragma unroll
    for (int i = 0; i < 4; i++) {
        float inv = 1.f / lrow[i];
#pragma unroll
        for (int gg = 0; gg < G; gg++) {
            float4 bv = *(const float4*)(bias_h + 64 * gg + 4 * tx);
            float2 e0 = f2unpack(o2[i][gg * 2 + 0]);
            float2 e1 = f2unpack(o2[i][gg * 2 + 1]);
            float v0 = fmaf(e0.x, inv, bv.x);
            float v1 = fmaf(e0.y, inv, bv.y);
            float v2 = fmaf(e1.x, inv, bv.z);
            float v3 = fmaf(e1.y, inv, bv.w);
            v0 = (v0 > 0.f) ? v0 : 0.01f * v0;
            v1 = (v1 > 0.f) ? v1 : 0.01f * v1;
            v2 = (v2 > 0.f) ? v2 : 0.01f * v2;
            v3 = (v3 > 0.f) ? v3 : 0.01f * v3;
            *(float4*)(Ob + (size_t)(n0 + ty * 4 + i) * fstride + 64 * gg + 4 * tx) =
                make_float4(v0, v1, v2, v3);
        }
    }
}

// ---------------------------------------------------------------------------
// Kernel 3: g_h2 = g_cat @ W_out   (M=16384, K=1024, Nc=64)
// Tile 128 rows x 64 cols; thread: 8 rows (ty*8+i) x 4 cols (4tx+q). f32x2.
// ---------------------------------------------------------------------------
__global__ __launch_bounds__(256) void gemm2_kernel(const float* __restrict__ Wout) {
    __shared__ float sA[128 * 64];  // 32 KB, stride 64
    __shared__ float sB[64 * 64];   // 16 KB, stride 64
    const int tid = threadIdx.x;
    const int tx = tid & 15, ty = tid >> 4;
    const int bn0 = blockIdx.x * 128;

    ull acc2[8][2];
#pragma unroll
    for (int i = 0; i < 8; i++) { acc2[i][0] = 0ull; acc2[i][1] = 0ull; }

    for (int k0 = 0; k0 < CAT_; k0 += 64) {
        for (int i = tid; i < 128 * 16; i += 256) {
            int r = i >> 4, c4 = i & 15;
            *(float4*)(sA + r * 64 + c4 * 4) =
                *(const float4*)(g_cat + (size_t)(bn0 + r) * CAT_ + k0 + c4 * 4);
        }
        for (int i = tid; i < 64 * 16; i += 256) {
            int r = i >> 4, c4 = i & 15;
            *(float4*)(sB + r * 64 + c4 * 4) =
                *(const float4*)(Wout + (size_t)(k0 + r) * COUT_ + c4 * 4);
        }
        __syncthreads();
#pragma unroll 2
        for (int k4 = 0; k4 < 64; k4 += 4) {
            float4 av[8];
#pragma unroll
            for (int i = 0; i < 8; i++)
                av[i] = *(const float4*)(sA + (ty * 8 + i) * 64 + k4);
#pragma unroll
            for (int k = 0; k < 4; k++) {
                ulonglong2 bv = *(const ulonglong2*)(sB + (k4 + k) * 64 + 4 * tx);
#pragma unroll
                for (int i = 0; i < 8; i++) {
                    float a = ((const float*)&av[i])[k];
                    ull pp = f2pack(a, a);
                    acc2[i][0] = ffma2(pp, bv.x, acc2[i][0]);
                    acc2[i][1] = ffma2(pp, bv.y, acc2[i][1]);
                }
            }
        }
        __syncthreads();
    }

#pragma unroll
    for (int i = 0; i < 8; i++) {
        float2 e0 = f2unpack(acc2[i][0]);
        float2 e1 = f2unpack(acc2[i][1]);
        *(float4*)(g_h2 + (size_t)(bn0 + ty * 8 + i) * COUT_ + 4 * tx) =
            make_float4(e0.x, e0.y, e1.x, e1.y);
    }
}

// ---------------------------------------------------------------------------
extern "C" void kernel_launch(void* const* d_in, const int* in_sizes, int n_in,
                              void* d_out, int out_size) {
    const float* flow_x = (const float*)d_in[0];
    const float* graph  = (const float*)d_in[1];
    const float* Wh     = (const float*)d_in[2];
    const float* bh     = (const float*)d_in[3];
    const float* W_out  = (const float*)d_in[4];
    const float* b_out  = (const float*)d_in[5];
    float* out = (float*)d_out;

    constexpr int SMEM128 = (64 * (128 + 4) * 2 + 64 * 68) * 4;  // 84992 B
    constexpr int SMEM64  = (64 * (64 + 4) * 2 + 64 * 68) * 4;   // 52224 B
    cudaFuncSetAttribute(attn_kernel<128, 1>, cudaFuncAttributeMaxDynamicSharedMemorySize, SMEM128);
    cudaFuncSetAttribute(attn_kernel<64, 2>,  cudaFuncAttributeMaxDynamicSharedMemorySize, SMEM64);

    gemm1_kernel<<<dim3(B_ * N_ / 64, H_), 256>>>(flow_x, Wh);
    attn_kernel<128, 1><<<dim3(N_ / 64, B_, H_), 256, SMEM128>>>(graph, bh, nullptr);
    gemm2_kernel<<<dim3(B_ * N_ / 128), 256>>>(W_out);
    attn_kernel<64, 2><<<dim3(N_ / 64, B_, 1), 256, SMEM64>>>(graph, b_out, out);
}

// round 7
// speedup vs baseline: 1.1409x; 1.0004x over previous
#include <cuda_runtime.h>
#include <math.h>

// Problem constants
constexpr int B_   = 16;
constexpr int N_   = 1024;
constexpr int CIN_ = 64;
constexpr int HID_ = 128;
constexpr int H_   = 8;
constexpr int COUT_= 64;
constexpr int CAT_ = HID_ * H_;   // 1024

typedef unsigned long long ull;

// Scratch (device globals — no allocation allowed)
__device__ float g_feat[B_ * N_ * CAT_];   // layer-1 per-head features, concat layout
__device__ float g_cat [B_ * N_ * CAT_];   // leakyrelu(attn1 + bh) in concat layout
__device__ float g_h2  [B_ * N_ * COUT_];  // layer-2 features

// ---- packed f32x2 helpers (sm_103a FFMA2: 2 fp32 FMAs per issued instr) ----
__device__ __forceinline__ ull f2pack(float lo, float hi) {
    ull r; asm("mov.b64 %0, {%1, %2};" : "=l"(r) : "f"(lo), "f"(hi)); return r;
}
__device__ __forceinline__ float2 f2unpack(ull v) {
    float2 r; asm("mov.b64 {%0, %1}, %2;" : "=f"(r.x), "=f"(r.y) : "l"(v)); return r;
}
__device__ __forceinline__ ull ffma2(ull a, ull b, ull c) {
    ull d; asm("fma.rn.f32x2 %0, %1, %2, %3;" : "=l"(d) : "l"(a), "l"(b), "l"(c)); return d;
}
__device__ __forceinline__ ull fmul2(ull a, ull b) {
    ull d; asm("mul.rn.f32x2 %0, %1, %2;" : "=l"(d) : "l"(a), "l"(b)); return d;
}

// ---------------------------------------------------------------------------
// Kernel 1: g_feat[bn][h*128 + c] = flow_x[bn] @ Wh[h]   (M=16384, K=64, Nc=128)
// Thread owns 4 rows (ty*4+i), cols 64g + 4tx + {0..3}, g<2. f32x2 inner.
// ---------------------------------------------------------------------------
__global__ __launch_bounds__(256) void gemm1_kernel(const float* __restrict__ x,
                                                    const float* __restrict__ Wh) {
    __shared__ float sX[64 * CIN_];    // 16 KB, stride 64
    __shared__ float sW[CIN_ * HID_];  // 32 KB, stride 128
    const int tid = threadIdx.x;
    const int tx = tid & 15, ty = tid >> 4;
    const int bn0 = blockIdx.x * 64;
    const int h = blockIdx.y;
    const float* Wp = Wh + (size_t)h * CIN_ * HID_;

    for (int i = tid; i < CIN_ * HID_ / 4; i += 256)
        *(float4*)(sW + i * 4) = *(const float4*)(Wp + i * 4);
    for (int i = tid; i < 64 * CIN_ / 4; i += 256) {
        int r = i >> 4, c4 = i & 15;
        *(float4*)(sX + r * CIN_ + c4 * 4) =
            *(const float4*)(x + (size_t)(bn0 + r) * CIN_ + c4 * 4);
    }
    __syncthreads();

    ull acc2[4][4];   // [row][g*2+p]
#pragma unroll
    for (int i = 0; i < 4; i++)
#pragma unroll
        for (int j = 0; j < 4; j++) acc2[i][j] = 0ull;

#pragma unroll 4
    for (int k4 = 0; k4 < CIN_; k4 += 4) {
        float4 av[4];
#pragma unroll
        for (int i = 0; i < 4; i++)
            av[i] = *(const float4*)(sX + (ty * 4 + i) * CIN_ + k4);
#pragma unroll
        for (int k = 0; k < 4; k++) {
            ulonglong2 wv[2];
#pragma unroll
            for (int g = 0; g < 2; g++)
                wv[g] = *(const ulonglong2*)(sW + (k4 + k) * HID_ + 64 * g + 4 * tx);
#pragma unroll
            for (int i = 0; i < 4; i++) {
                float a = ((const float*)&av[i])[k];
                ull pp = f2pack(a, a);
#pragma unroll
                for (int g = 0; g < 2; g++) {
                    acc2[i][g * 2 + 0] = ffma2(pp, wv[g].x, acc2[i][g * 2 + 0]);
                    acc2[i][g * 2 + 1] = ffma2(pp, wv[g].y, acc2[i][g * 2 + 1]);
                }
            }
        }
    }

#pragma unroll
    for (int i = 0; i < 4; i++)
#pragma unroll
        for (int g = 0; g < 2; g++) {
            float2 e0 = f2unpack(acc2[i][g * 2 + 0]);
            float2 e1 = f2unpack(acc2[i][g * 2 + 1]);
            float4 v = make_float4(e0.x, e0.y, e1.x, e1.y);
            *(float4*)(g_feat + (size_t)(bn0 + ty * 4 + i) * CAT_ + h * HID_ + 64 * g + 4 * tx) = v;
        }
}

// ---------------------------------------------------------------------------
// Fused masked-softmax attention (flash-style), Q=K=V=feat, f32x2 math.
//   LAYER 1: feat=g_feat (stride 1024), out=g_cat, epilogue = lrelu(o + bh[h])
//   LAYER 2: feat=g_h2  (stride 64),   out=d_out, epilogue = lrelu(o + b_out)
// Block: 64 query rows, 256 threads (16x16). S tile 4x4/thread (cols tx+16j),
// O cols owned as contiguous 4-blocks: 64g + 4tx + {0..3}.
// ---------------------------------------------------------------------------
template <int D, int LAYER>
__global__ __launch_bounds__(256, 2) void attn_kernel(const float* __restrict__ graph,
                                                      const float* __restrict__ bias,
                                                      float* __restrict__ out2) {
    constexpr int LD  = D + 4;   // float4-aligned
    constexpr int PLD = 68;
    constexpr int G   = D / 64;  // output col groups per thread (2 or 1)
    extern __shared__ float smem[];
    float* sQ = smem;
    float* sK = smem + 64 * LD;
    float* sP = sK + 64 * LD;

    const int tid = threadIdx.x;
    const int tx = tid & 15, ty = tid >> 4;
    const int n0 = blockIdx.x * 64;
    const int b  = blockIdx.y;
    const int h  = blockIdx.z;

    const int fstride = (LAYER == 1) ? CAT_ : COUT_;
    const float* feat = (LAYER == 1) ? g_feat : g_h2;
    float* outp       = (LAYER == 1) ? g_cat : out2;
    const float* Qb = feat + (size_t)b * N_ * fstride + h * D;
    float* Ob       = outp + (size_t)b * N_ * fstride + h * D;
    const float* bias_h = bias + h * D;

    // Q tile -> smem (vectorized)
    for (int i = tid; i < 64 * D / 4; i += 256) {
        int r = i / (D / 4), c4 = i % (D / 4);
        *(float4*)(sQ + r * LD + c4 * 4) =
            *(const float4*)(Qb + (size_t)(n0 + r) * fstride + c4 * 4);
    }

    ull o2[4][2 * G];
#pragma unroll
    for (int i = 0; i < 4; i++)
#pragma unroll
        for (int c = 0; c < 2 * G; c++) o2[i][c] = 0ull;
    float mrow[4] = {-INFINITY, -INFINITY, -INFINITY, -INFINITY};
    float lrow[4] = {0.f, 0.f, 0.f, 0.f};

    __syncthreads();

    for (int m0 = 0; m0 < N_; m0 += 64) {
        // K/V tile -> smem (vectorized)
        for (int i = tid; i < 64 * D / 4; i += 256) {
            int r = i / (D / 4), c4 = i % (D / 4);
            *(float4*)(sK + r * LD + c4 * 4) =
                *(const float4*)(Qb + (size_t)(m0 + r) * fstride + c4 * 4);
        }
        __syncthreads();

        // adjacency mask (L2-resident; overlaps with score compute)
        float g[4][4];
#pragma unroll
        for (int i = 0; i < 4; i++)
#pragma unroll
            for (int j = 0; j < 4; j++)
                g[i][j] = __ldg(&graph[(size_t)(n0 + ty * 4 + i) * N_ + m0 + tx + 16 * j]);

        // S = Q K^T, packed over d: acc holds (even-d, odd-d) partial sums
        ull acc2[4][4];
#pragma unroll
        for (int i = 0; i < 4; i++)
#pragma unroll
            for (int j = 0; j < 4; j++) acc2[i][j] = 0ull;

#pragma unroll 4
        for (int d0 = 0; d0 < D; d0 += 4) {
            ulonglong2 q2[4], k2[4];
#pragma unroll
            for (int i = 0; i < 4; i++)
                q2[i] = *(const ulonglong2*)(sQ + (ty * 4 + i) * LD + d0);
#pragma unroll
            for (int j = 0; j < 4; j++)
                k2[j] = *(const ulonglong2*)(sK + (tx + 16 * j) * LD + d0);
#pragma unroll
            for (int i = 0; i < 4; i++)
#pragma unroll
                for (int j = 0; j < 4; j++) {
                    acc2[i][j] = ffma2(q2[i].x, k2[j].x, acc2[i][j]);
                    acc2[i][j] = ffma2(q2[i].y, k2[j].y, acc2[i][j]);
                }
        }

        float s[4][4];
#pragma unroll
        for (int i = 0; i < 4; i++)
#pragma unroll
            for (int j = 0; j < 4; j++) {
                float2 e = f2unpack(acc2[i][j]);
                float v = e.x + e.y;
                s[i][j] = (g[i][j] != 0.f) ? v : -1e16f;
            }

        // online softmax per row (16 lanes share a row, contiguous in warp)
#pragma unroll
        for (int i = 0; i < 4; i++) {
            float tm = fmaxf(fmaxf(s[i][0], s[i][1]), fmaxf(s[i][2], s[i][3]));
#pragma unroll
            for (int off = 8; off >= 1; off >>= 1)
                tm = fmaxf(tm, __shfl_xor_sync(0xffffffffu, tm, off));
            float nm = fmaxf(mrow[i], tm);
            float scale = __expf(mrow[i] - nm);
            float ls = 0.f;
#pragma unroll
            for (int j = 0; j < 4; j++) {
                s[i][j] = __expf(s[i][j] - nm);
                ls += s[i][j];
            }
#pragma unroll
            for (int off = 8; off >= 1; off >>= 1)
                ls += __shfl_xor_sync(0xffffffffu, ls, off);
            lrow[i] = lrow[i] * scale + ls;
            mrow[i] = nm;
            ull sc2 = f2pack(scale, scale);
#pragma unroll
            for (int c = 0; c < 2 * G; c++) o2[i][c] = fmul2(o2[i][c], sc2);
#pragma unroll
            for (int j = 0; j < 4; j++) sP[(ty * 4 + i) * PLD + tx + 16 * j] = s[i][j];
        }
        __syncthreads();

        // O += P @ V  (V tile == K tile; cols 64g + 4tx, vector loads)
#pragma unroll 4
        for (int m4 = 0; m4 < 64; m4 += 4) {
            float4 pa[4];
#pragma unroll
            for (int i = 0; i < 4; i++)
                pa[i] = *(const float4*)(sP + (ty * 4 + i) * PLD + m4);
#pragma unroll
            for (int mm = 0; mm < 4; mm++) {
                ulonglong2 vv[G];
#pragma unroll
                for (int gg = 0; gg < G; gg++)
                    vv[gg] = *(const ulonglong2*)(sK + (m4 + mm) * LD + 64 * gg + 4 * tx);
#pragma unroll
                for (int i = 0; i < 4; i++) {
                    float p = ((const float*)&pa[i])[mm];
                    ull pp = f2pack(p, p);
#pragma unroll
                    for (int gg = 0; gg < G; gg++) {
                        o2[i][gg * 2 + 0] = ffma2(pp, vv[gg].x, o2[i][gg * 2 + 0]);
                        o2[i][gg * 2 + 1] = ffma2(pp, vv[gg].y, o2[i][gg * 2 + 1]);
                    }
                }
            }
        }
        __syncthreads();
    }

    // epilogue: normalize, bias, leaky_relu(0.01), vectorized store
#pragma unroll
    for (int i = 0; i < 4; i++) {
        float inv = 1.f / lrow[i];
#pragma unroll
        for (int gg = 0; gg < G; gg++) {
            float4 bv = *(const float4*)(bias_h + 64 * gg + 4 * tx);
            float2 e0 = f2unpack(o2[i][gg * 2 + 0]);
            float2 e1 = f2unpack(o2[i][gg * 2 + 1]);
            float v0 = fmaf(e0.x, inv, bv.x);
            float v1 = fmaf(e0.y, inv, bv.y);
            float v2 = fmaf(e1.x, inv, bv.z);
            float v3 = fmaf(e1.y, inv, bv.w);
            v0 = (v0 > 0.f) ? v0 : 0.01f * v0;
            v1 = (v1 > 0.f) ? v1 : 0.01f * v1;
            v2 = (v2 > 0.f) ? v2 : 0.01f * v2;
            v3 = (v3 > 0.f) ? v3 : 0.01f * v3;
            *(float4*)(Ob + (size_t)(n0 + ty * 4 + i) * fstride + 64 * gg + 4 * tx) =
                make_float4(v0, v1, v2, v3);
        }
    }
}

// ---------------------------------------------------------------------------
// Kernel 3: g_h2 = g_cat @ W_out   (M=16384, K=1024, Nc=64)
// Tile 128 rows x 64 cols; thread: 8 rows (ty*8+i) x 4 cols (4tx+q). f32x2.
// ---------------------------------------------------------------------------
__global__ __launch_bounds__(256) void gemm2_kernel(const float* __restrict__ Wout) {
    __shared__ float sA[128 * 64];  // 32 KB, stride 64
    __shared__ float sB[64 * 64];   // 16 KB, stride 64
    const int tid = threadIdx.x;
    const int tx = tid & 15, ty = tid >> 4;
    const int bn0 = blockIdx.x * 128;

    ull acc2[8][2];
#pragma unroll
    for (int i = 0; i < 8; i++) { acc2[i][0] = 0ull; acc2[i][1] = 0ull; }

    for (int k0 = 0; k0 < CAT_; k0 += 64) {
        for (int i = tid; i < 128 * 16; i += 256) {
            int r = i >> 4, c4 = i & 15;
            *(float4*)(sA + r * 64 + c4 * 4) =
                *(const float4*)(g_cat + (size_t)(bn0 + r) * CAT_ + k0 + c4 * 4);
        }
        for (int i = tid; i < 64 * 16; i += 256) {
            int r = i >> 4, c4 = i & 15;
            *(float4*)(sB + r * 64 + c4 * 4) =
                *(const float4*)(Wout + (size_t)(k0 + r) * COUT_ + c4 * 4);
        }
        __syncthreads();
#pragma unroll 2
        for (int k4 = 0; k4 < 64; k4 += 4) {
            float4 av[8];
#pragma unroll
            for (int i = 0; i < 8; i++)
                av[i] = *(const float4*)(sA + (ty * 8 + i) * 64 + k4);
#pragma unroll
            for (int k = 0; k < 4; k++) {
                ulonglong2 bv = *(const ulonglong2*)(sB + (k4 + k) * 64 + 4 * tx);
#pragma unroll
                for (int i = 0; i < 8; i++) {
                    float a = ((const float*)&av[i])[k];
                    ull pp = f2pack(a, a);
                    acc2[i][0] = ffma2(pp, bv.x, acc2[i][0]);
                    acc2[i][1] = ffma2(pp, bv.y, acc2[i][1]);
                }
            }
        }
        __syncthreads();
    }

#pragma unroll
    for (int i = 0; i < 8; i++) {
        float2 e0 = f2unpack(acc2[i][0]);
        float2 e1 = f2unpack(acc2[i][1]);
        *(float4*)(g_h2 + (size_t)(bn0 + ty * 8 + i) * COUT_ + 4 * tx) =
            make_float4(e0.x, e0.y, e1.x, e1.y);
    }
}

// ---------------------------------------------------------------------------
extern "C" void kernel_launch(void* const* d_in, const int* in_sizes, int n_in,
                              void* d_out, int out_size) {
    const float* flow_x = (const float*)d_in[0];
    const float* graph  = (const float*)d_in[1];
    const float* Wh     = (const float*)d_in[2];
    const float* bh     = (const float*)d_in[3];
    const float* W_out  = (const float*)d_in[4];
    const float* b_out  = (const float*)d_in[5];
    float* out = (float*)d_out;

    constexpr int SMEM128 = (64 * (128 + 4) * 2 + 64 * 68) * 4;  // 84992 B
    constexpr int SMEM64  = (64 * (64 + 4) * 2 + 64 * 68) * 4;   // 52224 B
    cudaFuncSetAttribute(attn_kernel<128, 1>, cudaFuncAttributeMaxDynamicSharedMemorySize, SMEM128);
    cudaFuncSetAttribute(attn_kernel<64, 2>,  cudaFuncAttributeMaxDynamicSharedMemorySize, SMEM64);

    gemm1_kernel<<<dim3(B_ * N_ / 64, H_), 256>>>(flow_x, Wh);
    attn_kernel<128, 1><<<dim3(N_ / 64, B_, H_), 256, SMEM128>>>(graph, bh, nullptr);
    gemm2_kernel<<<dim3(B_ * N_ / 128), 256>>>(W_out);
    attn_kernel<64, 2><<<dim3(N_ / 64, B_, 1), 256, SMEM64>>>(graph, b_out, out);
}

// round 8
// speedup vs baseline: 1.1416x; 1.0005x over previous
#include <cuda_runtime.h>
#include <math.h>

// Problem constants
constexpr int B_   = 16;
constexpr int N_   = 1024;
constexpr int CIN_ = 64;
constexpr int HID_ = 128;
constexpr int H_   = 8;
constexpr int COUT_= 64;
constexpr int CAT_ = HID_ * H_;   // 1024

typedef unsigned long long ull;

// Scratch (device globals — no allocation allowed)
__device__ float g_feat[B_ * N_ * CAT_];   // layer-1 per-head features, concat layout
__device__ float g_cat [B_ * N_ * CAT_];   // leakyrelu(attn1 + bh) in concat layout
__device__ float g_h2  [B_ * N_ * COUT_];  // layer-2 features

// ---- packed f32x2 helpers (sm_103a FFMA2: 2 fp32 FMAs per issued instr) ----
__device__ __forceinline__ ull f2pack(float lo, float hi) {
    ull r; asm("mov.b64 %0, {%1, %2};" : "=l"(r) : "f"(lo), "f"(hi)); return r;
}
__device__ __forceinline__ float2 f2unpack(ull v) {
    float2 r; asm("mov.b64 {%0, %1}, %2;" : "=f"(r.x), "=f"(r.y) : "l"(v)); return r;
}
__device__ __forceinline__ ull ffma2(ull a, ull b, ull c) {
    ull d; asm("fma.rn.f32x2 %0, %1, %2, %3;" : "=l"(d) : "l"(a), "l"(b), "l"(c)); return d;
}
__device__ __forceinline__ ull fmul2(ull a, ull b) {
    ull d; asm("mul.rn.f32x2 %0, %1, %2;" : "=l"(d) : "l"(a), "l"(b)); return d;
}

// ---------------------------------------------------------------------------
// Kernel 1: g_feat[bn][h*128 + c] = flow_x[bn] @ Wh[h]   (M=16384, K=64, Nc=128)
// Thread owns 4 rows (ty*4+i), cols 64g + 4tx + {0..3}, g<2. f32x2 inner.
// ---------------------------------------------------------------------------
__global__ __launch_bounds__(256) void gemm1_kernel(const float* __restrict__ x,
                                                    const float* __restrict__ Wh) {
    __shared__ float sX[64 * CIN_];    // 16 KB, stride 64
    __shared__ float sW[CIN_ * HID_];  // 32 KB, stride 128
    const int tid = threadIdx.x;
    const int tx = tid & 15, ty = tid >> 4;
    const int bn0 = blockIdx.x * 64;
    const int h = blockIdx.y;
    const float* Wp = Wh + (size_t)h * CIN_ * HID_;

    for (int i = tid; i < CIN_ * HID_ / 4; i += 256)
        *(float4*)(sW + i * 4) = *(const float4*)(Wp + i * 4);
    for (int i = tid; i < 64 * CIN_ / 4; i += 256) {
        int r = i >> 4, c4 = i & 15;
        *(float4*)(sX + r * CIN_ + c4 * 4) =
            *(const float4*)(x + (size_t)(bn0 + r) * CIN_ + c4 * 4);
    }
    __syncthreads();

    ull acc2[4][4];   // [row][g*2+p]
#pragma unroll
    for (int i = 0; i < 4; i++)
#pragma unroll
        for (int j = 0; j < 4; j++) acc2[i][j] = 0ull;

#pragma unroll 4
    for (int k4 = 0; k4 < CIN_; k4 += 4) {
        float4 av[4];
#pragma unroll
        for (int i = 0; i < 4; i++)
            av[i] = *(const float4*)(sX + (ty * 4 + i) * CIN_ + k4);
#pragma unroll
        for (int k = 0; k < 4; k++) {
            ulonglong2 wv[2];
#pragma unroll
            for (int g = 0; g < 2; g++)
                wv[g] = *(const ulonglong2*)(sW + (k4 + k) * HID_ + 64 * g + 4 * tx);
#pragma unroll
            for (int i = 0; i < 4; i++) {
                float a = ((const float*)&av[i])[k];
                ull pp = f2pack(a, a);
#pragma unroll
                for (int g = 0; g < 2; g++) {
                    acc2[i][g * 2 + 0] = ffma2(pp, wv[g].x, acc2[i][g * 2 + 0]);
                    acc2[i][g * 2 + 1] = ffma2(pp, wv[g].y, acc2[i][g * 2 + 1]);
                }
            }
        }
    }

#pragma unroll
    for (int i = 0; i < 4; i++)
#pragma unroll
        for (int g = 0; g < 2; g++) {
            float2 e0 = f2unpack(acc2[i][g * 2 + 0]);
            float2 e1 = f2unpack(acc2[i][g * 2 + 1]);
            float4 v = make_float4(e0.x, e0.y, e1.x, e1.y);
            *(float4*)(g_feat + (size_t)(bn0 + ty * 4 + i) * CAT_ + h * HID_ + 64 * g + 4 * tx) = v;
        }
}

// ---------------------------------------------------------------------------
// Fused masked-softmax attention (flash-style), Q=K=V=feat, f32x2 math.
//   LAYER 1: feat=g_feat (stride 1024), out=g_cat, epilogue = lrelu(o + bh[h])
//   LAYER 2: feat=g_h2  (stride 64),   out=d_out, epilogue = lrelu(o + b_out)
// Block: 64 query rows, 256 threads (16x16). S tile 4x4/thread (cols tx+16j),
// O cols owned as contiguous 4-blocks: 64g + 4tx + {0..3}.
// ---------------------------------------------------------------------------
template <int D, int LAYER>
__global__ __launch_bounds__(256, 2) void attn_kernel(const float* __restrict__ graph,
                                                      const float* __restrict__ bias,
                                                      float* __restrict__ out2) {
    constexpr int LD  = D + 4;   // float4-aligned
    constexpr int PLD = 68;
    constexpr int G   = D / 64;  // output col groups per thread (2 or 1)
    extern __shared__ float smem[];
    float* sQ = smem;
    float* sK = smem + 64 * LD;
    float* sP = sK + 64 * LD;

    const int tid = threadIdx.x;
    const int tx = tid & 15, ty = tid >> 4;
    const int n0 = blockIdx.x * 64;
    const int b  = blockIdx.y;
    const int h  = blockIdx.z;

    const int fstride = (LAYER == 1) ? CAT_ : COUT_;
    const float* feat = (LAYER == 1) ? g_feat : g_h2;
    float* outp       = (LAYER == 1) ? g_cat : out2;
    const float* Qb = feat + (size_t)b * N_ * fstride + h * D;
    float* Ob       = outp + (size_t)b * N_ * fstride + h * D;
    const float* bias_h = bias + h * D;

    // Q tile -> smem (vectorized)
    for (int i = tid; i < 64 * D / 4; i += 256) {
        int r = i / (D / 4), c4 = i % (D / 4);
        *(float4*)(sQ + r * LD + c4 * 4) =
            *(const float4*)(Qb + (size_t)(n0 + r) * fstride + c4 * 4);
    }

    ull o2[4][2 * G];
#pragma unroll
    for (int i = 0; i < 4; i++)
#pragma unroll
        for (int c = 0; c < 2 * G; c++) o2[i][c] = 0ull;
    float mrow[4] = {-INFINITY, -INFINITY, -INFINITY, -INFINITY};
    float lrow[4] = {0.f, 0.f, 0.f, 0.f};

    __syncthreads();

    for (int m0 = 0; m0 < N_; m0 += 64) {
        // K/V tile -> smem (vectorized)
        for (int i = tid; i < 64 * D / 4; i += 256) {
            int r = i / (D / 4), c4 = i % (D / 4);
            *(float4*)(sK + r * LD + c4 * 4) =
                *(const float4*)(Qb + (size_t)(m0 + r) * fstride + c4 * 4);
        }
        __syncthreads();

        // adjacency mask (L2-resident; overlaps with score compute)
        float g[4][4];
#pragma unroll
        for (int i = 0; i < 4; i++)
#pragma unroll
            for (int j = 0; j < 4; j++)
                g[i][j] = __ldg(&graph[(size_t)(n0 + ty * 4 + i) * N_ + m0 + tx + 16 * j]);

        // S = Q K^T, packed over d: acc holds (even-d, odd-d) partial sums
        ull acc2[4][4];
#pragma unroll
        for (int i = 0; i < 4; i++)
#pragma unroll
            for (int j = 0; j < 4; j++) acc2[i][j] = 0ull;

#pragma unroll 4
        for (int d0 = 0; d0 < D; d0 += 4) {
            ulonglong2 q2[4], k2[4];
#pragma unroll
            for (int i = 0; i < 4; i++)
                q2[i] = *(const ulonglong2*)(sQ + (ty * 4 + i) * LD + d0);
#pragma unroll
            for (int j = 0; j < 4; j++)
                k2[j] = *(const ulonglong2*)(sK + (tx + 16 * j) * LD + d0);
#pragma unroll
            for (int i = 0; i < 4; i++)
#pragma unroll
                for (int j = 0; j < 4; j++) {
                    acc2[i][j] = ffma2(q2[i].x, k2[j].x, acc2[i][j]);
                    acc2[i][j] = ffma2(q2[i].y, k2[j].y, acc2[i][j]);
                }
        }

        float s[4][4];
#pragma unroll
        for (int i = 0; i < 4; i++)
#pragma unroll
            for (int j = 0; j < 4; j++) {
                float2 e = f2unpack(acc2[i][j]);
                float v = e.x + e.y;
                s[i][j] = (g[i][j] != 0.f) ? v : -1e16f;
            }

        // online softmax per row (16 lanes share a row, contiguous in warp)
#pragma unroll
        for (int i = 0; i < 4; i++) {
            float tm = fmaxf(fmaxf(s[i][0], s[i][1]), fmaxf(s[i][2], s[i][3]));
#pragma unroll
            for (int off = 8; off >= 1; off >>= 1)
                tm = fmaxf(tm, __shfl_xor_sync(0xffffffffu, tm, off));
            float nm = fmaxf(mrow[i], tm);
            float scale = __expf(mrow[i] - nm);
            float ls = 0.f;
#pragma unroll
            for (int j = 0; j < 4; j++) {
                s[i][j] = __expf(s[i][j] - nm);
                ls += s[i][j];
            }
#pragma unroll
            for (int off = 8; off >= 1; off >>= 1)
                ls += __shfl_xor_sync(0xffffffffu, ls, off);
            lrow[i] = lrow[i] * scale + ls;
            mrow[i] = nm;
            ull sc2 = f2pack(scale, scale);
#pragma unroll
            for (int c = 0; c < 2 * G; c++) o2[i][c] = fmul2(o2[i][c], sc2);
#pragma unroll
            for (int j = 0; j < 4; j++) sP[(ty * 4 + i) * PLD + tx + 16 * j] = s[i][j];
        }
        __syncthreads();

        // O += P @ V  (V tile == K tile; cols 64g + 4tx, vector loads)
#pragma unroll 4
        for (int m4 = 0; m4 < 64; m4 += 4) {
            float4 pa[4];
#pragma unroll
            for (int i = 0; i < 4; i++)
                pa[i] = *(const float4*)(sP + (ty * 4 + i) * PLD + m4);
#pragma unroll
            for (int mm = 0; mm < 4; mm++) {
                ulonglong2 vv[G];
#pragma unroll
                for (int gg = 0; gg < G; gg++)
                    vv[gg] = *(const ulonglong2*)(sK + (m4 + mm) * LD + 64 * gg + 4 * tx);
#pragma unroll
                for (int i = 0; i < 4; i++) {
                    float p = ((const float*)&pa[i])[mm];
                    ull pp = f2pack(p, p);
#pragma unroll
                    for (int gg = 0; gg < G; gg++) {
                        o2[i][gg * 2 + 0] = ffma2(pp, vv[gg].x, o2[i][gg * 2 + 0]);
                        o2[i][gg * 2 + 1] = ffma2(pp, vv[gg].y, o2[i][gg * 2 + 1]);
                    }
                }
            }
        }
        __syncthreads();
    }

    // epilogue: normalize, bias, leaky_relu(0.01), vectorized store
#pragma unroll
    for (int i = 0; i < 4; i++) {
        float inv = 1.f / lrow[i];
#pragma unroll
        for (int gg = 0; gg < G; gg++) {
            float4 bv = *(const float4*)(bias_h + 64 * gg + 4 * tx);
            float2 e0 = f2unpack(o2[i][gg * 2 + 0]);
            float2 e1 = f2unpack(o2[i][gg * 2 + 1]);
            float v0 = fmaf(e0.x, inv, bv.x);
            float v1 = fmaf(e0.y, inv, bv.y);
            float v2 = fmaf(e1.x, inv, bv.z);
            float v3 = fmaf(e1.y, inv, bv.w);
            v0 = (v0 > 0.f) ? v0 : 0.01f * v0;
            v1 = (v1 > 0.f) ? v1 : 0.01f * v1;
            v2 = (v2 > 0.f) ? v2 : 0.01f * v2;
            v3 = (v3 > 0.f) ? v3 : 0.01f * v3;
            *(float4*)(Ob + (size_t)(n0 + ty * 4 + i) * fstride + 64 * gg + 4 * tx) =
                make_float4(v0, v1, v2, v3);
        }
    }
}

// ---------------------------------------------------------------------------
// Kernel 3: g_h2 = g_cat @ W_out   (M=16384, K=1024, Nc=64)
// Tile 128 rows x 64 cols; thread: 8 rows (ty*8+i) x 4 cols (4tx+q). f32x2.
// ---------------------------------------------------------------------------
__global__ __launch_bounds__(256) void gemm2_kernel(const float* __restrict__ Wout) {
    __shared__ float sA[128 * 64];  // 32 KB, stride 64
    __shared__ float sB[64 * 64];   // 16 KB, stride 64
    const int tid = threadIdx.x;
    const int tx = tid & 15, ty = tid >> 4;
    const int bn0 = blockIdx.x * 128;

    ull acc2[8][2];
#pragma unroll
    for (int i = 0; i < 8; i++) { acc2[i][0] = 0ull; acc2[i][1] = 0ull; }

    for (int k0 = 0; k0 < CAT_; k0 += 64) {
        for (int i = tid; i < 128 * 16; i += 256) {
            int r = i >> 4, c4 = i & 15;
            *(float4*)(sA + r * 64 + c4 * 4) =
                *(const float4*)(g_cat + (size_t)(bn0 + r) * CAT_ + k0 + c4 * 4);
        }
        for (int i = tid; i < 64 * 16; i += 256) {
            int r = i >> 4, c4 = i & 15;
            *(float4*)(sB + r * 64 + c4 * 4) =
                *(const float4*)(Wout + (size_t)(k0 + r) * COUT_ + c4 * 4);
        }
        __syncthreads();
#pragma unroll 2
        for (int k4 = 0; k4 < 64; k4 += 4) {
            float4 av[8];
#pragma unroll
            for (int i = 0; i < 8; i++)
                av[i] = *(const float4*)(sA + (ty * 8 + i) * 64 + k4);
#pragma unroll
            for (int k = 0; k < 4; k++) {
                ulonglong2 bv = *(const ulonglong2*)(sB + (k4 + k) * 64 + 4 * tx);
#pragma unroll
                for (int i = 0; i < 8; i++) {
                    float a = ((const float*)&av[i])[k];
                    ull pp = f2pack(a, a);
                    acc2[i][0] = ffma2(pp, bv.x, acc2[i][0]);
                    acc2[i][1] = ffma2(pp, bv.y, acc2[i][1]);
                }
            }
        }
        __syncthreads();
    }

#pragma unroll
    for (int i = 0; i < 8; i++) {
        float2 e0 = f2unpack(acc2[i][0]);
        float2 e1 = f2unpack(acc2[i][1]);
        *(float4*)(g_h2 + (size_t)(bn0 + ty * 8 + i) * COUT_ + 4 * tx) =
            make_float4(e0.x, e0.y, e1.x, e1.y);
    }
}

// ---------------------------------------------------------------------------
extern "C" void kernel_launch(void* const* d_in, const int* in_sizes, int n_in,
                              void* d_out, int out_size) {
    const float* flow_x = (const float*)d_in[0];
    const float* graph  = (const float*)d_in[1];
    const float* Wh     = (const float*)d_in[2];
    const float* bh     = (const float*)d_in[3];
    const float* W_out  = (const float*)d_in[4];
    const float* b_out  = (const float*)d_in[5];
    float* out = (float*)d_out;

    constexpr int SMEM128 = (64 * (128 + 4) * 2 + 64 * 68) * 4;  // 84992 B
    constexpr int SMEM64  = (64 * (64 + 4) * 2 + 64 * 68) * 4;   // 52224 B
    cudaFuncSetAttribute(attn_kernel<128, 1>, cudaFuncAttributeMaxDynamicSharedMemorySize, SMEM128);
    cudaFuncSetAttribute(attn_kernel<64, 2>,  cudaFuncAttributeMaxDynamicSharedMemorySize, SMEM64);

    gemm1_kernel<<<dim3(B_ * N_ / 64, H_), 256>>>(flow_x, Wh);
    attn_kernel<128, 1><<<dim3(N_ / 64, B_, H_), 256, SMEM128>>>(graph, bh, nullptr);
    gemm2_kernel<<<dim3(B_ * N_ / 128), 256>>>(W_out);
    attn_kernel<64, 2><<<dim3(N_ / 64, B_, 1), 256, SMEM64>>>(graph, b_out, out);
}

// round 11
// speedup vs baseline: 2.3050x; 2.0192x over previous
#include <cuda_runtime.h>
#include <cuda_fp16.h>
#include <math.h>
#include <stdint.h>

constexpr int B_=16, N_=1024, CIN_=64, HID_=128, H_=8, COUT_=64, CAT_=HID_*H_;
typedef unsigned long long ull;

// device scratch (no allocation allowed)
__device__ __half g_ka[(size_t)B_*H_*N_*HID_];   // feature limb hi, [bh][n][d]
__device__ __half g_kb[(size_t)B_*H_*N_*HID_];   // feature limb lo
__device__ uint32_t g_bits[N_*(N_/32)];          // adjacency bitmask
__device__ float g_cat[(size_t)B_*N_*CAT_];
__device__ float g_h2 [(size_t)B_*N_*COUT_];

// ---- f32x2 helpers (SIMT kernels) ----
__device__ __forceinline__ ull f2pack(float lo, float hi){ ull r; asm("mov.b64 %0, {%1, %2};" : "=l"(r) : "f"(lo), "f"(hi)); return r; }
__device__ __forceinline__ float2 f2unpack(ull v){ float2 r; asm("mov.b64 {%0, %1}, %2;" : "=f"(r.x), "=f"(r.y) : "l"(v)); return r; }
__device__ __forceinline__ ull ffma2(ull a, ull b, ull c){ ull d; asm("fma.rn.f32x2 %0, %1, %2, %3;" : "=l"(d) : "l"(a), "l"(b), "l"(c)); return d; }
__device__ __forceinline__ ull fmul2(ull a, ull b){ ull d; asm("mul.rn.f32x2 %0, %1, %2;" : "=l"(d) : "l"(a), "l"(b)); return d; }

__device__ __forceinline__ uint32_t smem_u32(const void* p){ uint32_t a; asm("{ .reg .u64 t; cvta.to.shared.u64 t, %1; cvt.u32.u64 %0, t; }" : "=r"(a) : "l"(p)); return a; }

// ---- baseline-PTX tensor ops (compute_103-safe) ----
__device__ __forceinline__ void ldsm4(uint32_t& r0, uint32_t& r1, uint32_t& r2, uint32_t& r3, uint32_t addr){
    asm volatile("ldmatrix.sync.aligned.m8n8.x4.shared.b16 {%0,%1,%2,%3}, [%4];"
        : "=r"(r0), "=r"(r1), "=r"(r2), "=r"(r3) : "r"(addr));
}
__device__ __forceinline__ void ldsm4t(uint32_t& r0, uint32_t& r1, uint32_t& r2, uint32_t& r3, uint32_t addr){
    asm volatile("ldmatrix.sync.aligned.m8n8.x4.trans.shared.b16 {%0,%1,%2,%3}, [%4];"
        : "=r"(r0), "=r"(r1), "=r"(r2), "=r"(r3) : "r"(addr));
}
__device__ __forceinline__ void mma16816(float* c, const uint32_t* a, uint32_t b0, uint32_t b1){
    asm volatile("mma.sync.aligned.m16n8k16.row.col.f32.f16.f16.f32 "
        "{%0,%1,%2,%3}, {%4,%5,%6,%7}, {%8,%9}, {%0,%1,%2,%3};"
        : "+f"(c[0]), "+f"(c[1]), "+f"(c[2]), "+f"(c[3])
        : "r"(a[0]), "r"(a[1]), "r"(a[2]), "r"(a[3]), "r"(b0), "r"(b1));
}
__device__ __forceinline__ void hsplit2(float x, float y, uint32_t& a, uint32_t& b){
    __half hx = __float2half_rn(x), hy = __float2half_rn(y);
    float rx = x - __half2float(hx), ry = y - __half2float(hy);
    __half lx = __float2half_rn(rx), ly = __float2half_rn(ry);
    a = ((uint32_t)__half_as_ushort(hy) << 16) | (uint32_t)__half_as_ushort(hx);
    b = ((uint32_t)__half_as_ushort(ly) << 16) | (uint32_t)__half_as_ushort(lx);
}

// graph -> bitmask
__global__ __launch_bounds__(256) void graph_bits_kernel(const float* __restrict__ graph){
    int w = blockIdx.x*256 + threadIdx.x;
    int row = w >> 5, c0 = (w & 31) * 32;
    uint32_t bits = 0;
#pragma unroll 8
    for (int j = 0; j < 32; j++)
        bits |= (graph[(size_t)row*N_ + c0 + j] != 0.f ? 1u : 0u) << j;
    g_bits[w] = bits;
}

// gemm1: per-head GEMM, epilogue splits features into fp16 2-limb arrays [bh][n][d]
__global__ __launch_bounds__(256) void gemm1_kernel(const float* __restrict__ x,
                                                    const float* __restrict__ Wh){
    __shared__ float sX[64*CIN_];
    __shared__ float sW[CIN_*HID_];
    const int tid = threadIdx.x, tx = tid & 15, ty = tid >> 4;
    const int bn0 = blockIdx.x * 64, h = blockIdx.y;
    const float* Wp = Wh + (size_t)h*CIN_*HID_;

    for (int i = tid; i < CIN_*HID_/4; i += 256)
        *(float4*)(sW + i*4) = *(const float4*)(Wp + i*4);
    for (int i = tid; i < 64*CIN_/4; i += 256){
        int r = i >> 4, c4 = i & 15;
        *(float4*)(sX + r*CIN_ + c4*4) = *(const float4*)(x + (size_t)(bn0+r)*CIN_ + c4*4);
    }
    __syncthreads();

    ull a2[4][4];
#pragma unroll
    for (int i = 0; i < 4; i++)
#pragma unroll
        for (int j = 0; j < 4; j++) a2[i][j] = 0ull;
#pragma unroll 4
    for (int k4 = 0; k4 < CIN_; k4 += 4){
        float4 av[4];
#pragma unroll
        for (int i = 0; i < 4; i++) av[i] = *(const float4*)(sX + (ty*4+i)*CIN_ + k4);
#pragma unroll
        for (int k = 0; k < 4; k++){
            ulonglong2 wv[2];
#pragma unroll
            for (int g = 0; g < 2; g++) wv[g] = *(const ulonglong2*)(sW + (k4+k)*HID_ + 64*g + 4*tx);
#pragma unroll
            for (int i = 0; i < 4; i++){
                float a = ((const float*)&av[i])[k];
                ull pp = f2pack(a, a);
#pragma unroll
                for (int g = 0; g < 2; g++){
                    a2[i][g*2+0] = ffma2(pp, wv[g].x, a2[i][g*2+0]);
                    a2[i][g*2+1] = ffma2(pp, wv[g].y, a2[i][g*2+1]);
                }
            }
        }
    }
#pragma unroll
    for (int i = 0; i < 4; i++){
        const int bn = bn0 + ty*4 + i, bb = bn >> 10, nn = bn & 1023;
        const size_t base = ((size_t)(bb*H_+h)*N_ + nn)*HID_;
#pragma unroll
        for (int g = 0; g < 2; g++){
            float2 e0 = f2unpack(a2[i][g*2+0]), e1 = f2unpack(a2[i][g*2+1]);
            uint32_t pa0, pb0, pa1, pb1;
            hsplit2(e0.x, e0.y, pa0, pb0);
            hsplit2(e1.x, e1.y, pa1, pb1);
            size_t ki = base + 64*g + 4*tx;
            *(uint2*)(g_ka + ki) = make_uint2(pa0, pa1);
            *(uint2*)(g_kb + ki) = make_uint2(pb0, pb1);
        }
    }
}

// layer-1 attention: fp16 2-limb emulated-fp32 flash attention via mma.sync
// CTA: 128 q rows x (b,h). 8 warps, warp owns 16 q rows. kv tiles of 64.
constexpr int LDR = 136;                 // padded row, fp16 units (272 B)
constexpr int SQ_BYTES = 128 * LDR * 2;  // 34816
constexpr int OFF_QA = 0, OFF_QB = SQ_BYTES, OFF_KA2 = 2*SQ_BYTES, OFF_KB2 = 2*SQ_BYTES + 64*LDR*2;
constexpr int SMEM_A1 = 2*SQ_BYTES + 2*64*LDR*2;  // 104448

__global__ __launch_bounds__(256, 1) void attn1_mma(const float* __restrict__ bh){
    extern __shared__ char sm[];
    const uint32_t sb = smem_u32(sm);
    const int tid = threadIdx.x, w = tid >> 5, lane = tid & 31;
    const int n0q = blockIdx.x * 128, b = blockIdx.y, h = blockIdx.z;
    const size_t bhoff = (size_t)(b*H_ + h);
    const __half* Ka = g_ka + bhoff*N_*HID_;
    const __half* Kb = g_kb + bhoff*N_*HID_;

    // stage Q (128x128 fp16 x2 limbs)
    for (int i = tid; i < 128*16; i += 256){
        int r = i >> 4, ch = i & 15;
        *(uint4*)(sm + OFF_QA + r*272 + ch*16) = *(const uint4*)(Ka + (size_t)(n0q+r)*HID_ + ch*8);
        *(uint4*)(sm + OFF_QB + r*272 + ch*16) = *(const uint4*)(Kb + (size_t)(n0q+r)*HID_ + ch*8);
    }
    __syncthreads();

    // Q fragments -> registers (held across all tiles)
    uint32_t qa[8][4], qb[8][4];
    {
        const int rowA = w*16 + (lane & 15);
        const int colA = (lane >> 4) * 8;
#pragma unroll
        for (int kt = 0; kt < 8; kt++){
            uint32_t adrA = sb + OFF_QA + rowA*272 + (kt*16 + colA)*2;
            ldsm4(qa[kt][0], qa[kt][1], qa[kt][2], qa[kt][3], adrA);
            uint32_t adrB = sb + OFF_QB + rowA*272 + (kt*16 + colA)*2;
            ldsm4(qb[kt][0], qb[kt][1], qb[kt][2], qb[kt][3], adrB);
        }
    }

    float o[16][4];
#pragma unroll
    for (int i = 0; i < 16; i++){ o[i][0]=0.f; o[i][1]=0.f; o[i][2]=0.f; o[i][3]=0.f; }
    float m0r = -INFINITY, m1r = -INFINITY, l0 = 0.f, l1 = 0.f;

    const int g = lane >> 2, q4 = lane & 3;
    const int row0 = n0q + w*16 + g;       // global q row (and row0+8)

    for (int t = 0; t < 16; t++){
        const int m0 = t*64;
        // stage K/V tile limbs (64x128 x2)
        for (int i = tid; i < 64*16; i += 256){
            int r = i >> 4, ch = i & 15;
            *(uint4*)(sm + OFF_KA2 + r*272 + ch*16) = *(const uint4*)(Ka + (size_t)(m0+r)*HID_ + ch*8);
            *(uint4*)(sm + OFF_KB2 + r*272 + ch*16) = *(const uint4*)(Kb + (size_t)(m0+r)*HID_ + ch*8);
        }
        __syncthreads();

        uint2 gb0 = *(const uint2*)&g_bits[(size_t)row0*32 + t*2];
        uint2 gb1 = *(const uint2*)&g_bits[(size_t)(row0+8)*32 + t*2];

        // S = Q K^T  (3 limb products)
        float s[8][4];
#pragma unroll
        for (int nt = 0; nt < 8; nt++){ s[nt][0]=0.f; s[nt][1]=0.f; s[nt][2]=0.f; s[nt][3]=0.f; }
        const int rowB = (lane & 7);
        const int colB8 = (lane >> 3) * 8;
#pragma unroll
        for (int nt = 0; nt < 8; nt++){
#pragma unroll
            for (int ktp = 0; ktp < 4; ktp++){
                uint32_t ka0, ka1, ka2, ka3, kb0, kb1, kb2, kb3;
                uint32_t adr = sb + OFF_KA2 + (nt*8 + rowB)*272 + (ktp*32 + colB8)*2;
                ldsm4(ka0, ka1, ka2, ka3, adr);
                adr = sb + OFF_KB2 + (nt*8 + rowB)*272 + (ktp*32 + colB8)*2;
                ldsm4(kb0, kb1, kb2, kb3, adr);
                const int kt = 2*ktp;
                mma16816(s[nt], qa[kt],   ka0, ka1);
                mma16816(s[nt], qa[kt],   kb0, kb1);
                mma16816(s[nt], qb[kt],   ka0, ka1);
                mma16816(s[nt], qa[kt+1], ka2, ka3);
                mma16816(s[nt], qa[kt+1], kb2, kb3);
                mma16816(s[nt], qb[kt+1], ka2, ka3);
            }
        }

        // mask + online softmax
        float tm0 = -INFINITY, tm1 = -INFINITY;
#pragma unroll
        for (int nt = 0; nt < 8; nt++){
            int c0 = nt*8 + 2*q4, c1 = c0 + 1;
            uint32_t w00 = (c0 < 32) ? gb0.x : gb0.y;
            uint32_t w10 = (c0 < 32) ? gb1.x : gb1.y;
            if (!((w00 >> (c0 & 31)) & 1u)) s[nt][0] = -1e16f;
            if (!((w00 >> (c1 & 31)) & 1u)) s[nt][1] = -1e16f;
            if (!((w10 >> (c0 & 31)) & 1u)) s[nt][2] = -1e16f;
            if (!((w10 >> (c1 & 31)) & 1u)) s[nt][3] = -1e16f;
            tm0 = fmaxf(tm0, fmaxf(s[nt][0], s[nt][1]));
            tm1 = fmaxf(tm1, fmaxf(s[nt][2], s[nt][3]));
        }
        tm0 = fmaxf(tm0, __shfl_xor_sync(0xffffffffu, tm0, 1));
        tm0 = fmaxf(tm0, __shfl_xor_sync(0xffffffffu, tm0, 2));
        tm1 = fmaxf(tm1, __shfl_xor_sync(0xffffffffu, tm1, 1));
        tm1 = fmaxf(tm1, __shfl_xor_sync(0xffffffffu, tm1, 2));
        float nm0 = fmaxf(m0r, tm0), nm1 = fmaxf(m1r, tm1);
        float sc0 = __expf(m0r - nm0), sc1 = __expf(m1r - nm1);
        m0r = nm0; m1r = nm1;
        l0 *= sc0; l1 *= sc1;
#pragma unroll
        for (int nt = 0; nt < 8; nt++){
            s[nt][0] = __expf(s[nt][0] - nm0);
            s[nt][1] = __expf(s[nt][1] - nm0);
            s[nt][2] = __expf(s[nt][2] - nm1);
            s[nt][3] = __expf(s[nt][3] - nm1);
            l0 += s[nt][0] + s[nt][1];
            l1 += s[nt][2] + s[nt][3];
        }
        // P limbs in A-fragment layout (C-frag == A-frag trick)
        uint32_t pa[4][4], pb[4][4];
#pragma unroll
        for (int kt = 0; kt < 4; kt++){
            hsplit2(s[2*kt][0],   s[2*kt][1],   pa[kt][0], pb[kt][0]);
            hsplit2(s[2*kt][2],   s[2*kt][3],   pa[kt][1], pb[kt][1]);
            hsplit2(s[2*kt+1][0], s[2*kt+1][1], pa[kt][2], pb[kt][2]);
            hsplit2(s[2*kt+1][2], s[2*kt+1][3], pa[kt][3], pb[kt][3]);
        }
        // rescale O
#pragma unroll
        for (int nt = 0; nt < 16; nt++){
            o[nt][0] *= sc0; o[nt][1] *= sc0; o[nt][2] *= sc1; o[nt][3] *= sc1;
        }
        // O += P V  (V = K tile, via ldmatrix.trans; 3 limb products)
        const int rV = (lane & 7) + ((lane & 8) ? 8 : 0);
        const int cV8 = (lane >> 4) * 8;
#pragma unroll
        for (int nt = 0; nt < 16; nt += 2){
#pragma unroll
            for (int kt = 0; kt < 4; kt++){
                uint32_t va0, va1, va2, va3, vb0, vb1, vb2, vb3;
                uint32_t adr = sb + OFF_KA2 + (kt*16 + rV)*272 + (nt*8 + cV8)*2;
                ldsm4t(va0, va1, va2, va3, adr);
                adr = sb + OFF_KB2 + (kt*16 + rV)*272 + (nt*8 + cV8)*2;
                ldsm4t(vb0, vb1, vb2, vb3, adr);
                mma16816(o[nt],   pa[kt], va0, va1);
                mma16816(o[nt],   pa[kt], vb0, vb1);
                mma16816(o[nt],   pb[kt], va0, va1);
                mma16816(o[nt+1], pa[kt], va2, va3);
                mma16816(o[nt+1], pa[kt], vb2, vb3);
                mma16816(o[nt+1], pb[kt], va2, va3);
            }
        }
        __syncthreads();
    }

    // epilogue
    l0 += __shfl_xor_sync(0xffffffffu, l0, 1);
    l0 += __shfl_xor_sync(0xffffffffu, l0, 2);
    l1 += __shfl_xor_sync(0xffffffffu, l1, 1);
    l1 += __shfl_xor_sync(0xffffffffu, l1, 2);
    float li0 = 1.f / l0, li1 = 1.f / l1;
    float* d0 = g_cat + ((size_t)b*N_ + row0)*CAT_ + h*HID_;
    float* d1 = g_cat + ((size_t)b*N_ + row0 + 8)*CAT_ + h*HID_;
    const float* bias = bh + h*HID_;
#pragma unroll
    for (int nt = 0; nt < 16; nt++){
        int c = nt*8 + 2*q4;
        float b0 = bias[c], b1 = bias[c+1];
        float v0 = fmaf(o[nt][0], li0, b0), v1 = fmaf(o[nt][1], li0, b1);
        float v2 = fmaf(o[nt][2], li1, b0), v3 = fmaf(o[nt][3], li1, b1);
        v0 = (v0 > 0.f) ? v0 : 0.01f*v0; v1 = (v1 > 0.f) ? v1 : 0.01f*v1;
        v2 = (v2 > 0.f) ? v2 : 0.01f*v2; v3 = (v3 > 0.f) ? v3 : 0.01f*v3;
        *(float2*)(d0 + c) = make_float2(v0, v1);
        *(float2*)(d1 + c) = make_float2(v2, v3);
    }
}

// gemm2: g_h2 = g_cat @ W_out (f32x2 SIMT, proven)
__global__ __launch_bounds__(256) void gemm2_kernel(const float* __restrict__ Wout){
    __shared__ float sA[128*64];
    __shared__ float sB[64*64];
    const int tid = threadIdx.x, tx = tid & 15, ty = tid >> 4;
    const int bn0 = blockIdx.x * 128;
    ull a2[8][2];
#pragma unroll
    for (int i = 0; i < 8; i++){ a2[i][0] = 0ull; a2[i][1] = 0ull; }
    for (int k0 = 0; k0 < CAT_; k0 += 64){
        for (int i = tid; i < 128*16; i += 256){
            int r = i >> 4, c4 = i & 15;
            *(float4*)(sA + r*64 + c4*4) = *(const float4*)(g_cat + (size_t)(bn0+r)*CAT_ + k0 + c4*4);
        }
        for (int i = tid; i < 64*16; i += 256){
            int r = i >> 4, c4 = i & 15;
            *(float4*)(sB + r*64 + c4*4) = *(const float4*)(Wout + (size_t)(k0+r)*COUT_ + c4*4);
        }
        __syncthreads();
#pragma unroll 2
        for (int k4 = 0; k4 < 64; k4 += 4){
            float4 av[8];
#pragma unroll
            for (int i = 0; i < 8; i++) av[i] = *(const float4*)(sA + (ty*8+i)*64 + k4);
#pragma unroll
            for (int k = 0; k < 4; k++){
                ulonglong2 bv = *(const ulonglong2*)(sB + (k4+k)*64 + 4*tx);
#pragma unroll
                for (int i = 0; i < 8; i++){
                    float a = ((const float*)&av[i])[k];
                    ull pp = f2pack(a, a);
                    a2[i][0] = ffma2(pp, bv.x, a2[i][0]);
                    a2[i][1] = ffma2(pp, bv.y, a2[i][1]);
                }
            }
        }
        __syncthreads();
    }
#pragma unroll
    for (int i = 0; i < 8; i++){
        float2 e0 = f2unpack(a2[i][0]), e1 = f2unpack(a2[i][1]);
        *(float4*)(g_h2 + (size_t)(bn0+ty*8+i)*COUT_ + 4*tx) = make_float4(e0.x, e0.y, e1.x, e1.y);
    }
}

// layer-2 attention (D=64), proven f32x2 SIMT path, writes d_out
__global__ __launch_bounds__(256, 2) void attn2_kernel(const float* __restrict__ graph,
                                                       const float* __restrict__ bias,
                                                       float* __restrict__ out2){
    constexpr int D = 64, LD = D + 4, PLD = 68;
    extern __shared__ float smem[];
    float* sQ = smem;
    float* sK = smem + 64*LD;
    float* sP = sK + 64*LD;
    const int tid = threadIdx.x, tx = tid & 15, ty = tid >> 4;
    const int n0 = blockIdx.x * 64, b = blockIdx.y;
    const float* Qb = g_h2 + (size_t)b*N_*COUT_;
    float* Ob = out2 + (size_t)b*N_*COUT_;

    for (int i = tid; i < 64*D/4; i += 256){
        int r = i / (D/4), c4 = i % (D/4);
        *(float4*)(sQ + r*LD + c4*4) = *(const float4*)(Qb + (size_t)(n0+r)*COUT_ + c4*4);
    }
    ull o2[4][2];
#pragma unroll
    for (int i = 0; i < 4; i++){ o2[i][0] = 0ull; o2[i][1] = 0ull; }
    float mrow[4] = {-INFINITY, -INFINITY, -INFINITY, -INFINITY};
    float lrow[4] = {0.f, 0.f, 0.f, 0.f};
    __syncthreads();

    for (int m0 = 0; m0 < N_; m0 += 64){
        for (int i = tid; i < 64*D/4; i += 256){
            int r = i / (D/4), c4 = i % (D/4);
            *(float4*)(sK + r*LD + c4*4) = *(const float4*)(Qb + (size_t)(m0+r)*COUT_ + c4*4);
        }
        __syncthreads();
        float g[4][4];
#pragma unroll
        for (int i = 0; i < 4; i++)
#pragma unroll
            for (int j = 0; j < 4; j++)
                g[i][j] = __ldg(&graph[(size_t)(n0+ty*4+i)*N_ + m0 + tx + 16*j]);
        ull acc2[4][4];
#pragma unroll
        for (int i = 0; i < 4; i++)
#pragma unroll
            for (int j = 0; j < 4; j++) acc2[i][j] = 0ull;
#pragma unroll 4
        for (int d0 = 0; d0 < D; d0 += 4){
            ulonglong2 q2[4], k2[4];
#pragma unroll
            for (int i = 0; i < 4; i++) q2[i] = *(const ulonglong2*)(sQ + (ty*4+i)*LD + d0);
#pragma unroll
            for (int j = 0; j < 4; j++) k2[j] = *(const ulonglong2*)(sK + (tx+16*j)*LD + d0);
#pragma unroll
            for (int i = 0; i < 4; i++)
#pragma unroll
                for (int j = 0; j < 4; j++){
                    acc2[i][j] = ffma2(q2[i].x, k2[j].x, acc2[i][j]);
                    acc2[i][j] = ffma2(q2[i].y, k2[j].y, acc2[i][j]);
                }
        }
        float s[4][4];
#pragma unroll
        for (int i = 0; i < 4; i++)
#pragma unroll
            for (int j = 0; j < 4; j++){
                float2 e = f2unpack(acc2[i][j]);
                float v = e.x + e.y;
                s[i][j] = (g[i][j] != 0.f) ? v : -1e16f;
            }
#pragma unroll
        for (int i = 0; i < 4; i++){
            float tm = fmaxf(fmaxf(s[i][0], s[i][1]), fmaxf(s[i][2], s[i][3]));
#pragma unroll
            for (int off = 8; off >= 1; off >>= 1) tm = fmaxf(tm, __shfl_xor_sync(0xffffffffu, tm, off));
            float nm = fmaxf(mrow[i], tm);
            float scale = __expf(mrow[i] - nm);
            float ls = 0.f;
#pragma unroll
            for (int j = 0; j < 4; j++){ s[i][j] = __expf(s[i][j] - nm); ls += s[i][j]; }
#pragma unroll
            for (int off = 8; off >= 1; off >>= 1) ls += __shfl_xor_sync(0xffffffffu, ls, off);
            lrow[i] = lrow[i]*scale + ls;
            mrow[i] = nm;
            ull sc2 = f2pack(scale, scale);
            o2[i][0] = fmul2(o2[i][0], sc2); o2[i][1] = fmul2(o2[i][1], sc2);
#pragma unroll
            for (int j = 0; j < 4; j++) sP[(ty*4+i)*PLD + tx + 16*j] = s[i][j];
        }
        __syncthreads();
#pragma unroll 4
        for (int m4 = 0; m4 < 64; m4 += 4){
            float4 pa[4];
#pragma unroll
            for (int i = 0; i < 4; i++) pa[i] = *(const float4*)(sP + (ty*4+i)*PLD + m4);
#pragma unroll
            for (int mm = 0; mm < 4; mm++){
                ulonglong2 vv = *(const ulonglong2*)(sK + (m4+mm)*LD + 4*tx);
#pragma unroll
                for (int i = 0; i < 4; i++){
                    float p = ((const float*)&pa[i])[mm];
                    ull pp = f2pack(p, p);
                    o2[i][0] = ffma2(pp, vv.x, o2[i][0]);
                    o2[i][1] = ffma2(pp, vv.y, o2[i][1]);
                }
            }
        }
        __syncthreads();
    }
#pragma unroll
    for (int i = 0; i < 4; i++){
        float inv = 1.f / lrow[i];
        float4 bv = *(const float4*)(bias + 4*tx);
        float2 e0 = f2unpack(o2[i][0]), e1 = f2unpack(o2[i][1]);
        float v0 = fmaf(e0.x, inv, bv.x), v1 = fmaf(e0.y, inv, bv.y);
        float v2 = fmaf(e1.x, inv, bv.z), v3 = fmaf(e1.y, inv, bv.w);
        v0 = (v0 > 0.f) ? v0 : 0.01f*v0; v1 = (v1 > 0.f) ? v1 : 0.01f*v1;
        v2 = (v2 > 0.f) ? v2 : 0.01f*v2; v3 = (v3 > 0.f) ? v3 : 0.01f*v3;
        *(float4*)(Ob + (size_t)(n0+ty*4+i)*COUT_ + 4*tx) = make_float4(v0, v1, v2, v3);
    }
}

extern "C" void kernel_launch(void* const* d_in, const int* in_sizes, int n_in,
                              void* d_out, int out_size){
    const float* flow_x = (const float*)d_in[0];
    const float* graph  = (const float*)d_in[1];
    const float* Wh     = (const float*)d_in[2];
    const float* bh     = (const float*)d_in[3];
    const float* W_out  = (const float*)d_in[4];
    const float* b_out  = (const float*)d_in[5];
    float* out = (float*)d_out;

    constexpr int SMEM64 = (64*(64+4)*2 + 64*68) * 4;
    cudaFuncSetAttribute(attn1_mma, cudaFuncAttributeMaxDynamicSharedMemorySize, SMEM_A1);
    cudaFuncSetAttribute(attn2_kernel, cudaFuncAttributeMaxDynamicSharedMemorySize, SMEM64);

    gemm1_kernel<<<dim3(B_*N_/64, H_), 256>>>(flow_x, Wh);
    graph_bits_kernel<<<128, 256>>>(graph);
    attn1_mma<<<dim3(N_/128, B_, H_), 256, SMEM_A1>>>(bh);
    gemm2_kernel<<<dim3(B_*N_/128), 256>>>(W_out);
    attn2_kernel<<<dim3(N_/64, B_), 256, SMEM64>>>(graph, b_out, out);
}

// round 13
// speedup vs baseline: 2.7740x; 1.2035x over previous
#include <cuda_runtime.h>
#include <cuda_fp16.h>
#include <math.h>
#include <stdint.h>

constexpr int B_=16, N_=1024, CIN_=64, HID_=128, H_=8, COUT_=64, CAT_=HID_*H_;
typedef unsigned long long ull;

// device scratch (no allocation allowed)
__device__ __half g_ka[(size_t)B_*H_*N_*HID_];   // layer-1 feature limb hi, [bh][n][d]
__device__ __half g_kb[(size_t)B_*H_*N_*HID_];   // layer-1 feature limb lo
__device__ __half g_ha[(size_t)B_*N_*COUT_];     // layer-2 feature limb hi, [b][n][d]
__device__ __half g_hb[(size_t)B_*N_*COUT_];     // layer-2 feature limb lo
__device__ uint32_t g_bits[N_*(N_/32)];          // adjacency bitmask
__device__ float g_cat[(size_t)B_*N_*CAT_];      // layer-1 activated output (fp32)

// ---- f32x2 helpers (SIMT kernels) ----
__device__ __forceinline__ ull f2pack(float lo, float hi){ ull r; asm("mov.b64 %0, {%1, %2};" : "=l"(r) : "f"(lo), "f"(hi)); return r; }
__device__ __forceinline__ float2 f2unpack(ull v){ float2 r; asm("mov.b64 {%0, %1}, %2;" : "=f"(r.x), "=f"(r.y) : "l"(v)); return r; }
__device__ __forceinline__ ull ffma2(ull a, ull b, ull c){ ull d; asm("fma.rn.f32x2 %0, %1, %2, %3;" : "=l"(d) : "l"(a), "l"(b), "l"(c)); return d; }

__device__ __forceinline__ uint32_t smem_u32(const void* p){ uint32_t a; asm("{ .reg .u64 t; cvta.to.shared.u64 t, %1; cvt.u32.u64 %0, t; }" : "=r"(a) : "l"(p)); return a; }

// ---- baseline-PTX tensor + async ops (compute_103-safe) ----
__device__ __forceinline__ void ldsm4(uint32_t& r0, uint32_t& r1, uint32_t& r2, uint32_t& r3, uint32_t addr){
    asm volatile("ldmatrix.sync.aligned.m8n8.x4.shared.b16 {%0,%1,%2,%3}, [%4];"
        : "=r"(r0), "=r"(r1), "=r"(r2), "=r"(r3) : "r"(addr));
}
__device__ __forceinline__ void ldsm4t(uint32_t& r0, uint32_t& r1, uint32_t& r2, uint32_t& r3, uint32_t addr){
    asm volatile("ldmatrix.sync.aligned.m8n8.x4.trans.shared.b16 {%0,%1,%2,%3}, [%4];"
        : "=r"(r0), "=r"(r1), "=r"(r2), "=r"(r3) : "r"(addr));
}
__device__ __forceinline__ void mma16816(float* c, const uint32_t* a, uint32_t b0, uint32_t b1){
    asm volatile("mma.sync.aligned.m16n8k16.row.col.f32.f16.f16.f32 "
        "{%0,%1,%2,%3}, {%4,%5,%6,%7}, {%8,%9}, {%0,%1,%2,%3};"
        : "+f"(c[0]), "+f"(c[1]), "+f"(c[2]), "+f"(c[3])
        : "r"(a[0]), "r"(a[1]), "r"(a[2]), "r"(a[3]), "r"(b0), "r"(b1));
}
__device__ __forceinline__ void hsplit2(float x, float y, uint32_t& a, uint32_t& b){
    __half hx = __float2half_rn(x), hy = __float2half_rn(y);
    float rx = x - __half2float(hx), ry = y - __half2float(hy);
    __half lx = __float2half_rn(rx), ly = __float2half_rn(ry);
    a = ((uint32_t)__half_as_ushort(hy) << 16) | (uint32_t)__half_as_ushort(hx);
    b = ((uint32_t)__half_as_ushort(ly) << 16) | (uint32_t)__half_as_ushort(lx);
}
__device__ __forceinline__ void cpa16(uint32_t saddr, const void* g){
    asm volatile("cp.async.cg.shared.global [%0], [%1], 16;" :: "r"(saddr), "l"(g));
}
#define CPA_COMMIT() asm volatile("cp.async.commit_group;" ::: "memory")
#define CPA_WAIT(n)  asm volatile("cp.async.wait_group %0;" :: "n"(n) : "memory")

// graph -> bitmask
__global__ __launch_bounds__(256) void graph_bits_kernel(const float* __restrict__ graph){
    int w = blockIdx.x*256 + threadIdx.x;
    int row = w >> 5, c0 = (w & 31) * 32;
    uint32_t bits = 0;
#pragma unroll 8
    for (int j = 0; j < 32; j++)
        bits |= (graph[(size_t)row*N_ + c0 + j] != 0.f ? 1u : 0u) << j;
    g_bits[w] = bits;
}

// gemm1: per-head GEMM, epilogue splits features into fp16 2-limb arrays [bh][n][d]
__global__ __launch_bounds__(256) void gemm1_kernel(const float* __restrict__ x,
                                                    const float* __restrict__ Wh){
    __shared__ float sX[64*CIN_];
    __shared__ float sW[CIN_*HID_];
    const int tid = threadIdx.x, tx = tid & 15, ty = tid >> 4;
    const int bn0 = blockIdx.x * 64, h = blockIdx.y;
    const float* Wp = Wh + (size_t)h*CIN_*HID_;

    for (int i = tid; i < CIN_*HID_/4; i += 256)
        *(float4*)(sW + i*4) = *(const float4*)(Wp + i*4);
    for (int i = tid; i < 64*CIN_/4; i += 256){
        int r = i >> 4, c4 = i & 15;
        *(float4*)(sX + r*CIN_ + c4*4) = *(const float4*)(x + (size_t)(bn0+r)*CIN_ + c4*4);
    }
    __syncthreads();

    ull a2[4][4];
#pragma unroll
    for (int i = 0; i < 4; i++)
#pragma unroll
        for (int j = 0; j < 4; j++) a2[i][j] = 0ull;
#pragma unroll 4
    for (int k4 = 0; k4 < CIN_; k4 += 4){
        float4 av[4];
#pragma unroll
        for (int i = 0; i < 4; i++) av[i] = *(const float4*)(sX + (ty*4+i)*CIN_ + k4);
#pragma unroll
        for (int k = 0; k < 4; k++){
            ulonglong2 wv[2];
#pragma unroll
            for (int g = 0; g < 2; g++) wv[g] = *(const ulonglong2*)(sW + (k4+k)*HID_ + 64*g + 4*tx);
#pragma unroll
            for (int i = 0; i < 4; i++){
                float a = ((const float*)&av[i])[k];
                ull pp = f2pack(a, a);
#pragma unroll
                for (int g = 0; g < 2; g++){
                    a2[i][g*2+0] = ffma2(pp, wv[g].x, a2[i][g*2+0]);
                    a2[i][g*2+1] = ffma2(pp, wv[g].y, a2[i][g*2+1]);
                }
            }
        }
    }
#pragma unroll
    for (int i = 0; i < 4; i++){
        const int bn = bn0 + ty*4 + i, bb = bn >> 10, nn = bn & 1023;
        const size_t base = ((size_t)(bb*H_+h)*N_ + nn)*HID_;
#pragma unroll
        for (int g = 0; g < 2; g++){
            float2 e0 = f2unpack(a2[i][g*2+0]), e1 = f2unpack(a2[i][g*2+1]);
            uint32_t pa0, pb0, pa1, pb1;
            hsplit2(e0.x, e0.y, pa0, pb0);
            hsplit2(e1.x, e1.y, pa1, pb1);
            size_t ki = base + 64*g + 4*tx;
            *(uint2*)(g_ka + ki) = make_uint2(pa0, pa1);
            *(uint2*)(g_kb + ki) = make_uint2(pb0, pb1);
        }
    }
}

// ---------------------------------------------------------------------------
// Unified fp16 2-limb emulated-fp32 flash attention via mma.sync.
// CTA: 128 q rows x (b[,h]). 8 warps, warp owns 16 q rows. kv tiles of 64.
// cp.async double-buffered K/V staging.
// ---------------------------------------------------------------------------
template <int D, int LAYER>
__global__ __launch_bounds__(256, 1) void attn_mma(const float* __restrict__ bias_g,
                                                   float* __restrict__ out2){
    constexpr int KT = D / 16;           // A-frag k-tiles
    constexpr int NO = D / 8;            // output col groups of 8
    constexpr int CH = D / 8;            // 16B chunks per row
    constexpr int LDRB = (D + 8) * 2;    // padded row bytes
    constexpr int QLIMB = 128 * LDRB;
    constexpr int KLIMB = 64 * LDRB;
    constexpr int KBUF = 2 * KLIMB;      // (limb a, limb b) per buffer
    constexpr int OFF_K = 2 * QLIMB;

    extern __shared__ char sm[];
    const uint32_t sb = smem_u32(sm);
    const int tid = threadIdx.x, w = tid >> 5, lane = tid & 31;
    const int n0q = blockIdx.x * 128, b = blockIdx.y, h = blockIdx.z;
    const __half* Fa;
    const __half* Fb;
    if (LAYER == 1){
        const size_t bhoff = (size_t)(b*H_ + h);
        Fa = g_ka + bhoff*N_*HID_;
        Fb = g_kb + bhoff*N_*HID_;
    } else {
        Fa = g_ha + (size_t)b*N_*COUT_;
        Fb = g_hb + (size_t)b*N_*COUT_;
    }

    // stage Q (128 x D fp16 x2 limbs)
    for (int i = tid; i < 128*CH; i += 256){
        int r = i / CH, ch = i % CH;
        *(uint4*)(sm + 0     + r*LDRB + ch*16) = *(const uint4*)(Fa + (size_t)(n0q+r)*D + ch*8);
        *(uint4*)(sm + QLIMB + r*LDRB + ch*16) = *(const uint4*)(Fb + (size_t)(n0q+r)*D + ch*8);
    }
    __syncthreads();

    // Q fragments -> registers
    uint32_t qa[KT][4], qb[KT][4];
    {
        const int rowA = w*16 + (lane & 15);
        const int colA = (lane >> 4) * 8;
#pragma unroll
        for (int kt = 0; kt < KT; kt++){
            ldsm4(qa[kt][0], qa[kt][1], qa[kt][2], qa[kt][3], sb + 0     + rowA*LDRB + (kt*16 + colA)*2);
            ldsm4(qb[kt][0], qb[kt][1], qb[kt][2], qb[kt][3], sb + QLIMB + rowA*LDRB + (kt*16 + colA)*2);
        }
    }

    float o[NO][4];
#pragma unroll
    for (int i = 0; i < NO; i++){ o[i][0]=0.f; o[i][1]=0.f; o[i][2]=0.f; o[i][3]=0.f; }
    float m0r = -INFINITY, m1r = -INFINITY, l0 = 0.f, l1 = 0.f;

    const int g = lane >> 2, q4 = lane & 3;
    const int row0 = n0q + w*16 + g;

    // prefetch tile 0
    for (int i = tid; i < 64*CH; i += 256){
        int r = i / CH, ch = i % CH;
        cpa16(sb + OFF_K + r*LDRB + ch*16,         Fa + (size_t)r*D + ch*8);
        cpa16(sb + OFF_K + KLIMB + r*LDRB + ch*16, Fb + (size_t)r*D + ch*8);
    }
    CPA_COMMIT();

    for (int t = 0; t < 16; t++){
        const uint32_t kbase = sb + OFF_K + (t & 1)*KBUF;
        if (t < 15){
            const int m1 = (t+1)*64;
            const uint32_t nb = sb + OFF_K + ((t+1) & 1)*KBUF;
            for (int i = tid; i < 64*CH; i += 256){
                int r = i / CH, ch = i % CH;
                cpa16(nb + r*LDRB + ch*16,         Fa + (size_t)(m1+r)*D + ch*8);
                cpa16(nb + KLIMB + r*LDRB + ch*16, Fb + (size_t)(m1+r)*D + ch*8);
            }
            CPA_COMMIT();
            CPA_WAIT(1);
        } else {
            CPA_WAIT(0);
        }
        __syncthreads();

        uint2 gb0 = *(const uint2*)&g_bits[(size_t)row0*32 + t*2];
        uint2 gb1 = *(const uint2*)&g_bits[(size_t)(row0+8)*32 + t*2];

        // S = Q K^T (3 limb products)
        float s[8][4];
#pragma unroll
        for (int nt = 0; nt < 8; nt++){ s[nt][0]=0.f; s[nt][1]=0.f; s[nt][2]=0.f; s[nt][3]=0.f; }
        const int rowB = (lane & 7);
        const int colB8 = (lane >> 3) * 8;
#pragma unroll
        for (int nt = 0; nt < 8; nt++){
#pragma unroll
            for (int ktp = 0; ktp < KT/2; ktp++){
                uint32_t ka0, ka1, ka2, ka3, kb0, kb1, kb2, kb3;
                ldsm4(ka0, ka1, ka2, ka3, kbase + (nt*8 + rowB)*LDRB + (ktp*32 + colB8)*2);
                ldsm4(kb0, kb1, kb2, kb3, kbase + KLIMB + (nt*8 + rowB)*LDRB + (ktp*32 + colB8)*2);
                const int kt = 2*ktp;
                mma16816(s[nt], qa[kt],   ka0, ka1);
                mma16816(s[nt], qa[kt],   kb0, kb1);
                mma16816(s[nt], qb[kt],   ka0, ka1);
                mma16816(s[nt], qa[kt+1], ka2, ka3);
                mma16816(s[nt], qa[kt+1], kb2, kb3);
                mma16816(s[nt], qb[kt+1], ka2, ka3);
            }
        }

        // mask + online softmax
        float tm0 = -INFINITY, tm1 = -INFINITY;
#pragma unroll
        for (int nt = 0; nt < 8; nt++){
            int c0 = nt*8 + 2*q4, c1 = c0 + 1;
            uint32_t w00 = (c0 < 32) ? gb0.x : gb0.y;
            uint32_t w10 = (c0 < 32) ? gb1.x : gb1.y;
            if (!((w00 >> (c0 & 31)) & 1u)) s[nt][0] = -1e16f;
            if (!((w00 >> (c1 & 31)) & 1u)) s[nt][1] = -1e16f;
            if (!((w10 >> (c0 & 31)) & 1u)) s[nt][2] = -1e16f;
            if (!((w10 >> (c1 & 31)) & 1u)) s[nt][3] = -1e16f;
            tm0 = fmaxf(tm0, fmaxf(s[nt][0], s[nt][1]));
            tm1 = fmaxf(tm1, fmaxf(s[nt][2], s[nt][3]));
        }
        tm0 = fmaxf(tm0, __shfl_xor_sync(0xffffffffu, tm0, 1));
        tm0 = fmaxf(tm0, __shfl_xor_sync(0xffffffffu, tm0, 2));
        tm1 = fmaxf(tm1, __shfl_xor_sync(0xffffffffu, tm1, 1));
        tm1 = fmaxf(tm1, __shfl_xor_sync(0xffffffffu, tm1, 2));
        float nm0 = fmaxf(m0r, tm0), nm1 = fmaxf(m1r, tm1);
        float sc0 = __expf(m0r - nm0), sc1 = __expf(m1r - nm1);
        m0r = nm0; m1r = nm1;
        l0 *= sc0; l1 *= sc1;
#pragma unroll
        for (int nt = 0; nt < 8; nt++){
            s[nt][0] = __expf(s[nt][0] - nm0);
            s[nt][1] = __expf(s[nt][1] - nm0);
            s[nt][2] = __expf(s[nt][2] - nm1);
            s[nt][3] = __expf(s[nt][3] - nm1);
            l0 += s[nt][0] + s[nt][1];
            l1 += s[nt][2] + s[nt][3];
        }
        // P limbs in A-fragment layout
        uint32_t pa[4][4], pb[4][4];
#pragma unroll
        for (int kt = 0; kt < 4; kt++){
            hsplit2(s[2*kt][0],   s[2*kt][1],   pa[kt][0], pb[kt][0]);
            hsplit2(s[2*kt][2],   s[2*kt][3],   pa[kt][1], pb[kt][1]);
            hsplit2(s[2*kt+1][0], s[2*kt+1][1], pa[kt][2], pb[kt][2]);
            hsplit2(s[2*kt+1][2], s[2*kt+1][3], pa[kt][3], pb[kt][3]);
        }
#pragma unroll
        for (int nt = 0; nt < NO; nt++){
            o[nt][0] *= sc0; o[nt][1] *= sc0; o[nt][2] *= sc1; o[nt][3] *= sc1;
        }
        // O += P V (V = K tile via ldmatrix.trans; 3 limb products)
        const int rV = (lane & 7) + ((lane & 8) ? 8 : 0);
        const int cV8 = (lane >> 4) * 8;
#pragma unroll
        for (int nt = 0; nt < NO; nt += 2){
#pragma unroll
            for (int kt = 0; kt < 4; kt++){
                uint32_t va0, va1, va2, va3, vb0, vb1, vb2, vb3;
                ldsm4t(va0, va1, va2, va3, kbase + (kt*16 + rV)*LDRB + (nt*8 + cV8)*2);
                ldsm4t(vb0, vb1, vb2, vb3, kbase + KLIMB + (kt*16 + rV)*LDRB + (nt*8 + cV8)*2);
                mma16816(o[nt],   pa[kt], va0, va1);
                mma16816(o[nt],   pa[kt], vb0, vb1);
                mma16816(o[nt],   pb[kt], va0, va1);
                mma16816(o[nt+1], pa[kt], va2, va3);
                mma16816(o[nt+1], pa[kt], vb2, vb3);
                mma16816(o[nt+1], pb[kt], va2, va3);
            }
        }
        __syncthreads();
    }

    // epilogue
    l0 += __shfl_xor_sync(0xffffffffu, l0, 1);
    l0 += __shfl_xor_sync(0xffffffffu, l0, 2);
    l1 += __shfl_xor_sync(0xffffffffu, l1, 1);
    l1 += __shfl_xor_sync(0xffffffffu, l1, 2);
    float li0 = 1.f / l0, li1 = 1.f / l1;
    float *d0, *d1;
    const float* bias;
    if (LAYER == 1){
        d0 = g_cat + ((size_t)b*N_ + row0)*CAT_ + h*HID_;
        d1 = g_cat + ((size_t)b*N_ + row0 + 8)*CAT_ + h*HID_;
        bias = bias_g + h*HID_;
    } else {
        d0 = out2 + ((size_t)b*N_ + row0)*COUT_;
        d1 = out2 + ((size_t)b*N_ + row0 + 8)*COUT_;
        bias = bias_g;
    }
#pragma unroll
    for (int nt = 0; nt < NO; nt++){
        int c = nt*8 + 2*q4;
        float b0 = bias[c], b1 = bias[c+1];
        float v0 = fmaf(o[nt][0], li0, b0), v1 = fmaf(o[nt][1], li0, b1);
        float v2 = fmaf(o[nt][2], li1, b0), v3 = fmaf(o[nt][3], li1, b1);
        v0 = (v0 > 0.f) ? v0 : 0.01f*v0; v1 = (v1 > 0.f) ? v1 : 0.01f*v1;
        v2 = (v2 > 0.f) ? v2 : 0.01f*v2; v3 = (v3 > 0.f) ? v3 : 0.01f*v3;
        *(float2*)(d0 + c) = make_float2(v0, v1);
        *(float2*)(d1 + c) = make_float2(v2, v3);
    }
}

// gemm2: g_cat @ W_out -> fp16 limb arrays g_ha/g_hb. 64-row tiles, 256 CTAs.
__global__ __launch_bounds__(256) void gemm2_kernel(const float* __restrict__ Wout){
    __shared__ float sA[64*64];
    __shared__ float sB[64*64];
    const int tid = threadIdx.x, tx = tid & 15, ty = tid >> 4;
    const int bn0 = blockIdx.x * 64;
    ull a2[4][2];
#pragma unroll
    for (int i = 0; i < 4; i++){ a2[i][0] = 0ull; a2[i][1] = 0ull; }
    for (int k0 = 0; k0 < CAT_; k0 += 64){
        for (int i = tid; i < 64*16; i += 256){
            int r = i >> 4, c4 = i & 15;
            *(float4*)(sA + r*64 + c4*4) = *(const float4*)(g_cat + (size_t)(bn0+r)*CAT_ + k0 + c4*4);
            *(float4*)(sB + r*64 + c4*4) = *(const float4*)(Wout + (size_t)(k0+r)*COUT_ + c4*4);
        }
        __syncthreads();
#pragma unroll 4
        for (int k4 = 0; k4 < 64; k4 += 4){
            float4 av[4];
#pragma unroll
            for (int i = 0; i < 4; i++) av[i] = *(const float4*)(sA + (ty*4+i)*64 + k4);
#pragma unroll
            for (int k = 0; k < 4; k++){
                ulonglong2 bv = *(const ulonglong2*)(sB + (k4+k)*64 + 4*tx);
#pragma unroll
                for (int i = 0; i < 4; i++){
                    float a = ((const float*)&av[i])[k];
                    ull pp = f2pack(a, a);
                    a2[i][0] = ffma2(pp, bv.x, a2[i][0]);
                    a2[i][1] = ffma2(pp, bv.y, a2[i][1]);
                }
            }
        }
        __syncthreads();
    }
#pragma unroll
    for (int i = 0; i < 4; i++){
        float2 e0 = f2unpack(a2[i][0]), e1 = f2unpack(a2[i][1]);
        uint32_t pa0, pb0, pa1, pb1;
        hsplit2(e0.x, e0.y, pa0, pb0);
        hsplit2(e1.x, e1.y, pa1, pb1);
        size_t hi = (size_t)(bn0 + ty*4 + i)*COUT_ + 4*tx;
        *(uint2*)(g_ha + hi) = make_uint2(pa0, pa1);
        *(uint2*)(g_hb + hi) = make_uint2(pb0, pb1);
    }
}

extern "C" void kernel_launch(void* const* d_in, const int* in_sizes, int n_in,
                              void* d_out, int out_size){
    const float* flow_x = (const float*)d_in[0];
    const float* graph  = (const float*)d_in[1];
    const float* Wh     = (const float*)d_in[2];
    const float* bh     = (const float*)d_in[3];
    const float* W_out  = (const float*)d_in[4];
    const float* b_out  = (const float*)d_in[5];
    float* out = (float*)d_out;

    // dynamic smem: 2 Q limbs + 2 double-buffered (K limb pair)
    constexpr int SM1 = 2*128*(128+8)*2 + 2*2*64*(128+8)*2;  // 139264
    constexpr int SM2 = 2*128*(64+8)*2  + 2*2*64*(64+8)*2;   // 73728
    cudaFuncSetAttribute(attn_mma<128,1>, cudaFuncAttributeMaxDynamicSharedMemorySize, SM1);
    cudaFuncSetAttribute(attn_mma<64,2>,  cudaFuncAttributeMaxDynamicSharedMemorySize, SM2);

    gemm1_kernel<<<dim3(B_*N_/64, H_), 256>>>(flow_x, Wh);
    graph_bits_kernel<<<128, 256>>>(graph);
    attn_mma<128,1><<<dim3(N_/128, B_, H_), 256, SM1>>>(bh, nullptr);
    gemm2_kernel<<<dim3(B_*N_/64), 256>>>(W_out);
    attn_mma<64,2><<<dim3(N_/128, B_, 1), 256, SM2>>>(b_out, out);
}

// round 14
// speedup vs baseline: 2.9309x; 1.0565x over previous
#include <cuda_runtime.h>
#include <cuda_fp16.h>
#include <math.h>
#include <stdint.h>

constexpr int B_=16, N_=1024, CIN_=64, HID_=128, H_=8, COUT_=64, CAT_=HID_*H_;
typedef unsigned long long ull;

// device scratch (no allocation allowed)
__device__ __half g_ka[(size_t)B_*H_*N_*HID_];   // L1 feature limb hi, [bh][n][d]
__device__ __half g_kb[(size_t)B_*H_*N_*HID_];   // L1 feature limb lo
__device__ __half g_ca[(size_t)B_*N_*CAT_];      // L1 activated output limb hi, [b][n][hd]
__device__ __half g_cb[(size_t)B_*N_*CAT_];      // L1 activated output limb lo
__device__ __half g_wa[CAT_*COUT_];              // W_out limb hi [k][n]
__device__ __half g_wb[CAT_*COUT_];              // W_out limb lo
__device__ __half g_ha[(size_t)B_*N_*COUT_];     // L2 feature limb hi
__device__ __half g_hb[(size_t)B_*N_*COUT_];     // L2 feature limb lo
__device__ uint32_t g_bits[N_*(N_/32)];          // adjacency bitmask

// ---- f32x2 helpers ----
__device__ __forceinline__ ull f2pack(float lo, float hi){ ull r; asm("mov.b64 %0, {%1, %2};" : "=l"(r) : "f"(lo), "f"(hi)); return r; }
__device__ __forceinline__ float2 f2unpack(ull v){ float2 r; asm("mov.b64 {%0, %1}, %2;" : "=f"(r.x), "=f"(r.y) : "l"(v)); return r; }
__device__ __forceinline__ ull ffma2(ull a, ull b, ull c){ ull d; asm("fma.rn.f32x2 %0, %1, %2, %3;" : "=l"(d) : "l"(a), "l"(b), "l"(c)); return d; }

__device__ __forceinline__ uint32_t smem_u32(const void* p){ uint32_t a; asm("{ .reg .u64 t; cvta.to.shared.u64 t, %1; cvt.u32.u64 %0, t; }" : "=r"(a) : "l"(p)); return a; }

// ---- baseline-PTX tensor + async ops (compute_103-safe) ----
__device__ __forceinline__ void ldsm4(uint32_t& r0, uint32_t& r1, uint32_t& r2, uint32_t& r3, uint32_t addr){
    asm volatile("ldmatrix.sync.aligned.m8n8.x4.shared.b16 {%0,%1,%2,%3}, [%4];"
        : "=r"(r0), "=r"(r1), "=r"(r2), "=r"(r3) : "r"(addr));
}
__device__ __forceinline__ void ldsm4t(uint32_t& r0, uint32_t& r1, uint32_t& r2, uint32_t& r3, uint32_t addr){
    asm volatile("ldmatrix.sync.aligned.m8n8.x4.trans.shared.b16 {%0,%1,%2,%3}, [%4];"
        : "=r"(r0), "=r"(r1), "=r"(r2), "=r"(r3) : "r"(addr));
}
__device__ __forceinline__ void mma16816(float* c, const uint32_t* a, uint32_t b0, uint32_t b1){
    asm volatile("mma.sync.aligned.m16n8k16.row.col.f32.f16.f16.f32 "
        "{%0,%1,%2,%3}, {%4,%5,%6,%7}, {%8,%9}, {%0,%1,%2,%3};"
        : "+f"(c[0]), "+f"(c[1]), "+f"(c[2]), "+f"(c[3])
        : "r"(a[0]), "r"(a[1]), "r"(a[2]), "r"(a[3]), "r"(b0), "r"(b1));
}
__device__ __forceinline__ void hsplit2(float x, float y, uint32_t& a, uint32_t& b){
    __half hx = __float2half_rn(x), hy = __float2half_rn(y);
    float rx = x - __half2float(hx), ry = y - __half2float(hy);
    __half lx = __float2half_rn(rx), ly = __float2half_rn(ry);
    a = ((uint32_t)__half_as_ushort(hy) << 16) | (uint32_t)__half_as_ushort(hx);
    b = ((uint32_t)__half_as_ushort(ly) << 16) | (uint32_t)__half_as_ushort(lx);
}
__device__ __forceinline__ void cpa16(uint32_t saddr, const void* g){
    asm volatile("cp.async.cg.shared.global [%0], [%1], 16;" :: "r"(saddr), "l"(g));
}
#define CPA_COMMIT() asm volatile("cp.async.commit_group;" ::: "memory")
#define CPA_WAIT(n)  asm volatile("cp.async.wait_group %0;" :: "n"(n) : "memory")

// graph -> bitmask
__global__ __launch_bounds__(256) void graph_bits_kernel(const float* __restrict__ graph){
    int w = blockIdx.x*256 + threadIdx.x;
    int row = w >> 5, c0 = (w & 31) * 32;
    uint32_t bits = 0;
#pragma unroll 8
    for (int j = 0; j < 32; j++)
        bits |= (graph[(size_t)row*N_ + c0 + j] != 0.f ? 1u : 0u) << j;
    g_bits[w] = bits;
}

// W_out -> fp16 limbs
__global__ __launch_bounds__(256) void wsplit_kernel(const float* __restrict__ Wout){
    int i = blockIdx.x*256 + threadIdx.x;   // 32768 pairs
    float2 v = *(const float2*)(Wout + i*2);
    uint32_t a, b;
    hsplit2(v.x, v.y, a, b);
    *(uint32_t*)(g_wa + i*2) = a;
    *(uint32_t*)(g_wb + i*2) = b;
}

// gemm1: per-head GEMM, epilogue splits features into fp16 2-limb arrays [bh][n][d]
__global__ __launch_bounds__(256) void gemm1_kernel(const float* __restrict__ x,
                                                    const float* __restrict__ Wh){
    __shared__ float sX[64*CIN_];
    __shared__ float sW[CIN_*HID_];
    const int tid = threadIdx.x, tx = tid & 15, ty = tid >> 4;
    const int bn0 = blockIdx.x * 64, h = blockIdx.y;
    const float* Wp = Wh + (size_t)h*CIN_*HID_;

    for (int i = tid; i < CIN_*HID_/4; i += 256)
        *(float4*)(sW + i*4) = *(const float4*)(Wp + i*4);
    for (int i = tid; i < 64*CIN_/4; i += 256){
        int r = i >> 4, c4 = i & 15;
        *(float4*)(sX + r*CIN_ + c4*4) = *(const float4*)(x + (size_t)(bn0+r)*CIN_ + c4*4);
    }
    __syncthreads();

    ull a2[4][4];
#pragma unroll
    for (int i = 0; i < 4; i++)
#pragma unroll
        for (int j = 0; j < 4; j++) a2[i][j] = 0ull;
#pragma unroll 4
    for (int k4 = 0; k4 < CIN_; k4 += 4){
        float4 av[4];
#pragma unroll
        for (int i = 0; i < 4; i++) av[i] = *(const float4*)(sX + (ty*4+i)*CIN_ + k4);
#pragma unroll
        for (int k = 0; k < 4; k++){
            ulonglong2 wv[2];
#pragma unroll
            for (int g = 0; g < 2; g++) wv[g] = *(const ulonglong2*)(sW + (k4+k)*HID_ + 64*g + 4*tx);
#pragma unroll
            for (int i = 0; i < 4; i++){
                float a = ((const float*)&av[i])[k];
                ull pp = f2pack(a, a);
#pragma unroll
                for (int g = 0; g < 2; g++){
                    a2[i][g*2+0] = ffma2(pp, wv[g].x, a2[i][g*2+0]);
                    a2[i][g*2+1] = ffma2(pp, wv[g].y, a2[i][g*2+1]);
                }
            }
        }
    }
#pragma unroll
    for (int i = 0; i < 4; i++){
        const int bn = bn0 + ty*4 + i, bb = bn >> 10, nn = bn & 1023;
        const size_t base = ((size_t)(bb*H_+h)*N_ + nn)*HID_;
#pragma unroll
        for (int g = 0; g < 2; g++){
            float2 e0 = f2unpack(a2[i][g*2+0]), e1 = f2unpack(a2[i][g*2+1]);
            uint32_t pa0, pb0, pa1, pb1;
            hsplit2(e0.x, e0.y, pa0, pb0);
            hsplit2(e1.x, e1.y, pa1, pb1);
            size_t ki = base + 64*g + 4*tx;
            *(uint2*)(g_ka + ki) = make_uint2(pa0, pa1);
            *(uint2*)(g_kb + ki) = make_uint2(pb0, pb1);
        }
    }
}

// ---------------------------------------------------------------------------
// Unified fp16 2-limb emulated-fp32 flash attention via mma.sync.
// QROWS q-rows per CTA, WARPS = QROWS/16 warps. kv tiles of 64.
// cp.async double-buffered K/V staging.
// ---------------------------------------------------------------------------
template <int D, int LAYER, int QROWS>
__global__ __launch_bounds__(QROWS*2, 1) void attn_mma(const float* __restrict__ bias_g,
                                                       float* __restrict__ out2){
    constexpr int THREADS = QROWS*2;
    constexpr int KT = D / 16;
    constexpr int NO = D / 8;
    constexpr int CH = D / 8;
    constexpr int LDRB = (D + 8) * 2;
    constexpr int QLIMB = QROWS * LDRB;
    constexpr int KLIMB = 64 * LDRB;
    constexpr int KBUF = 2 * KLIMB;
    constexpr int OFF_K = 2 * QLIMB;

    extern __shared__ char sm[];
    const uint32_t sb = smem_u32(sm);
    const int tid = threadIdx.x, w = tid >> 5, lane = tid & 31;
    const int n0q = blockIdx.x * QROWS, b = blockIdx.y, h = blockIdx.z;
    const __half* Fa;
    const __half* Fb;
    if (LAYER == 1){
        const size_t bhoff = (size_t)(b*H_ + h);
        Fa = g_ka + bhoff*N_*HID_;
        Fb = g_kb + bhoff*N_*HID_;
    } else {
        Fa = g_ha + (size_t)b*N_*COUT_;
        Fb = g_hb + (size_t)b*N_*COUT_;
    }

    // stage Q
    for (int i = tid; i < QROWS*CH; i += THREADS){
        int r = i / CH, ch = i % CH;
        *(uint4*)(sm + 0     + r*LDRB + ch*16) = *(const uint4*)(Fa + (size_t)(n0q+r)*D + ch*8);
        *(uint4*)(sm + QLIMB + r*LDRB + ch*16) = *(const uint4*)(Fb + (size_t)(n0q+r)*D + ch*8);
    }
    __syncthreads();

    uint32_t qa[KT][4], qb[KT][4];
    {
        const int rowA = w*16 + (lane & 15);
        const int colA = (lane >> 4) * 8;
#pragma unroll
        for (int kt = 0; kt < KT; kt++){
            ldsm4(qa[kt][0], qa[kt][1], qa[kt][2], qa[kt][3], sb + 0     + rowA*LDRB + (kt*16 + colA)*2);
            ldsm4(qb[kt][0], qb[kt][1], qb[kt][2], qb[kt][3], sb + QLIMB + rowA*LDRB + (kt*16 + colA)*2);
        }
    }

    float o[NO][4];
#pragma unroll
    for (int i = 0; i < NO; i++){ o[i][0]=0.f; o[i][1]=0.f; o[i][2]=0.f; o[i][3]=0.f; }
    float m0r = -INFINITY, m1r = -INFINITY, l0 = 0.f, l1 = 0.f;

    const int g = lane >> 2, q4 = lane & 3;
    const int row0 = n0q + w*16 + g;

    for (int i = tid; i < 64*CH; i += THREADS){
        int r = i / CH, ch = i % CH;
        cpa16(sb + OFF_K + r*LDRB + ch*16,         Fa + (size_t)r*D + ch*8);
        cpa16(sb + OFF_K + KLIMB + r*LDRB + ch*16, Fb + (size_t)r*D + ch*8);
    }
    CPA_COMMIT();

    for (int t = 0; t < 16; t++){
        const uint32_t kbase = sb + OFF_K + (t & 1)*KBUF;
        if (t < 15){
            const int m1 = (t+1)*64;
            const uint32_t nb = sb + OFF_K + ((t+1) & 1)*KBUF;
            for (int i = tid; i < 64*CH; i += THREADS){
                int r = i / CH, ch = i % CH;
                cpa16(nb + r*LDRB + ch*16,         Fa + (size_t)(m1+r)*D + ch*8);
                cpa16(nb + KLIMB + r*LDRB + ch*16, Fb + (size_t)(m1+r)*D + ch*8);
            }
            CPA_COMMIT();
            CPA_WAIT(1);
        } else {
            CPA_WAIT(0);
        }
        __syncthreads();

        uint2 gb0 = *(const uint2*)&g_bits[(size_t)row0*32 + t*2];
        uint2 gb1 = *(const uint2*)&g_bits[(size_t)(row0+8)*32 + t*2];

        float s[8][4];
#pragma unroll
        for (int nt = 0; nt < 8; nt++){ s[nt][0]=0.f; s[nt][1]=0.f; s[nt][2]=0.f; s[nt][3]=0.f; }
        const int rowB = (lane & 7);
        const int colB8 = (lane >> 3) * 8;
#pragma unroll
        for (int nt = 0; nt < 8; nt++){
#pragma unroll
            for (int ktp = 0; ktp < KT/2; ktp++){
                uint32_t ka0, ka1, ka2, ka3, kb0, kb1, kb2, kb3;
                ldsm4(ka0, ka1, ka2, ka3, kbase + (nt*8 + rowB)*LDRB + (ktp*32 + colB8)*2);
                ldsm4(kb0, kb1, kb2, kb3, kbase + KLIMB + (nt*8 + rowB)*LDRB + (ktp*32 + colB8)*2);
                const int kt = 2*ktp;
                mma16816(s[nt], qa[kt],   ka0, ka1);
                mma16816(s[nt], qa[kt],   kb0, kb1);
                mma16816(s[nt], qb[kt],   ka0, ka1);
                mma16816(s[nt], qa[kt+1], ka2, ka3);
                mma16816(s[nt], qa[kt+1], kb2, kb3);
                mma16816(s[nt], qb[kt+1], ka2, ka3);
            }
        }

        float tm0 = -INFINITY, tm1 = -INFINITY;
#pragma unroll
        for (int nt = 0; nt < 8; nt++){
            int c0 = nt*8 + 2*q4, c1 = c0 + 1;
            uint32_t w00 = (c0 < 32) ? gb0.x : gb0.y;
            uint32_t w10 = (c0 < 32) ? gb1.x : gb1.y;
            if (!((w00 >> (c0 & 31)) & 1u)) s[nt][0] = -1e16f;
            if (!((w00 >> (c1 & 31)) & 1u)) s[nt][1] = -1e16f;
            if (!((w10 >> (c0 & 31)) & 1u)) s[nt][2] = -1e16f;
            if (!((w10 >> (c1 & 31)) & 1u)) s[nt][3] = -1e16f;
            tm0 = fmaxf(tm0, fmaxf(s[nt][0], s[nt][1]));
            tm1 = fmaxf(tm1, fmaxf(s[nt][2], s[nt][3]));
        }
        tm0 = fmaxf(tm0, __shfl_xor_sync(0xffffffffu, tm0, 1));
        tm0 = fmaxf(tm0, __shfl_xor_sync(0xffffffffu, tm0, 2));
        tm1 = fmaxf(tm1, __shfl_xor_sync(0xffffffffu, tm1, 1));
        tm1 = fmaxf(tm1, __shfl_xor_sync(0xffffffffu, tm1, 2));
        float nm0 = fmaxf(m0r, tm0), nm1 = fmaxf(m1r, tm1);
        float sc0 = __expf(m0r - nm0), sc1 = __expf(m1r - nm1);
        m0r = nm0; m1r = nm1;
        l0 *= sc0; l1 *= sc1;
#pragma unroll
        for (int nt = 0; nt < 8; nt++){
            s[nt][0] = __expf(s[nt][0] - nm0);
            s[nt][1] = __expf(s[nt][1] - nm0);
            s[nt][2] = __expf(s[nt][2] - nm1);
            s[nt][3] = __expf(s[nt][3] - nm1);
            l0 += s[nt][0] + s[nt][1];
            l1 += s[nt][2] + s[nt][3];
        }
        uint32_t pa[4][4], pb[4][4];
#pragma unroll
        for (int kt = 0; kt < 4; kt++){
            hsplit2(s[2*kt][0],   s[2*kt][1],   pa[kt][0], pb[kt][0]);
            hsplit2(s[2*kt][2],   s[2*kt][3],   pa[kt][1], pb[kt][1]);
            hsplit2(s[2*kt+1][0], s[2*kt+1][1], pa[kt][2], pb[kt][2]);
            hsplit2(s[2*kt+1][2], s[2*kt+1][3], pa[kt][3], pb[kt][3]);
        }
#pragma unroll
        for (int nt = 0; nt < NO; nt++){
            o[nt][0] *= sc0; o[nt][1] *= sc0; o[nt][2] *= sc1; o[nt][3] *= sc1;
        }
        const int rV = (lane & 7) + ((lane & 8) ? 8 : 0);
        const int cV8 = (lane >> 4) * 8;
#pragma unroll
        for (int nt = 0; nt < NO; nt += 2){
#pragma unroll
            for (int kt = 0; kt < 4; kt++){
                uint32_t va0, va1, va2, va3, vb0, vb1, vb2, vb3;
                ldsm4t(va0, va1, va2, va3, kbase + (kt*16 + rV)*LDRB + (nt*8 + cV8)*2);
                ldsm4t(vb0, vb1, vb2, vb3, kbase + KLIMB + (kt*16 + rV)*LDRB + (nt*8 + cV8)*2);
                mma16816(o[nt],   pa[kt], va0, va1);
                mma16816(o[nt],   pa[kt], vb0, vb1);
                mma16816(o[nt],   pb[kt], va0, va1);
                mma16816(o[nt+1], pa[kt], va2, va3);
                mma16816(o[nt+1], pa[kt], vb2, vb3);
                mma16816(o[nt+1], pb[kt], va2, va3);
            }
        }
        __syncthreads();
    }

    // epilogue
    l0 += __shfl_xor_sync(0xffffffffu, l0, 1);
    l0 += __shfl_xor_sync(0xffffffffu, l0, 2);
    l1 += __shfl_xor_sync(0xffffffffu, l1, 1);
    l1 += __shfl_xor_sync(0xffffffffu, l1, 2);
    float li0 = 1.f / l0, li1 = 1.f / l1;
    if (LAYER == 1){
        const float* bias = bias_g + h*HID_;
        const size_t i0 = ((size_t)b*N_ + row0)*CAT_ + h*HID_;
        const size_t i1 = ((size_t)b*N_ + row0 + 8)*CAT_ + h*HID_;
#pragma unroll
        for (int nt = 0; nt < NO; nt++){
            int c = nt*8 + 2*q4;
            float b0 = bias[c], b1 = bias[c+1];
            float v0 = fmaf(o[nt][0], li0, b0), v1 = fmaf(o[nt][1], li0, b1);
            float v2 = fmaf(o[nt][2], li1, b0), v3 = fmaf(o[nt][3], li1, b1);
            v0 = (v0 > 0.f) ? v0 : 0.01f*v0; v1 = (v1 > 0.f) ? v1 : 0.01f*v1;
            v2 = (v2 > 0.f) ? v2 : 0.01f*v2; v3 = (v3 > 0.f) ? v3 : 0.01f*v3;
            uint32_t ua, ub;
            hsplit2(v0, v1, ua, ub);
            *(uint32_t*)(g_ca + i0 + c) = ua;
            *(uint32_t*)(g_cb + i0 + c) = ub;
            hsplit2(v2, v3, ua, ub);
            *(uint32_t*)(g_ca + i1 + c) = ua;
            *(uint32_t*)(g_cb + i1 + c) = ub;
        }
    } else {
        const float* bias = bias_g;
        float* d0 = out2 + ((size_t)b*N_ + row0)*COUT_;
        float* d1 = out2 + ((size_t)b*N_ + row0 + 8)*COUT_;
#pragma unroll
        for (int nt = 0; nt < NO; nt++){
            int c = nt*8 + 2*q4;
            float b0 = bias[c], b1 = bias[c+1];
            float v0 = fmaf(o[nt][0], li0, b0), v1 = fmaf(o[nt][1], li0, b1);
            float v2 = fmaf(o[nt][2], li1, b0), v3 = fmaf(o[nt][3], li1, b1);
            v0 = (v0 > 0.f) ? v0 : 0.01f*v0; v1 = (v1 > 0.f) ? v1 : 0.01f*v1;
            v2 = (v2 > 0.f) ? v2 : 0.01f*v2; v3 = (v3 > 0.f) ? v3 : 0.01f*v3;
            *(float2*)(d0 + c) = make_float2(v0, v1);
            *(float2*)(d1 + c) = make_float2(v2, v3);
        }
    }
}

// ---------------------------------------------------------------------------
// gemm2 via HMMA: g_ha/g_hb = (g_ca,g_cb) @ (g_wa,g_wb), 3-product limb emu.
// CTA: 64 rows x 64 cols, 4 warps. k chunks of 64, cp.async double-buffered.
// ---------------------------------------------------------------------------
constexpr int G2_LDR = (64 + 8) * 2;            // 144 B rows
constexpr int G2_A = 64 * G2_LDR;               // one A limb tile
constexpr int G2_CHUNK = 2*G2_A + 2*G2_A;       // A(a,b) + W(a,b) = 4 tiles
__global__ __launch_bounds__(128, 1) void gemm2_mma(){
    extern __shared__ char sm[];
    const uint32_t sb = smem_u32(sm);
    const int tid = threadIdx.x, w = tid >> 5, lane = tid & 31;
    const int bn0 = blockIdx.x * 64;

    float o[8][4];
#pragma unroll
    for (int i = 0; i < 8; i++){ o[i][0]=0.f; o[i][1]=0.f; o[i][2]=0.f; o[i][3]=0.f; }

    // prefetch chunk 0
    for (int i = tid; i < 64*8; i += 128){
        int r = i >> 3, ch = i & 7;
        cpa16(sb + 0*G2_A + r*G2_LDR + ch*16, g_ca + (size_t)(bn0+r)*CAT_ + ch*8);
        cpa16(sb + 1*G2_A + r*G2_LDR + ch*16, g_cb + (size_t)(bn0+r)*CAT_ + ch*8);
        cpa16(sb + 2*G2_A + r*G2_LDR + ch*16, g_wa + (size_t)r*COUT_ + ch*8);
        cpa16(sb + 3*G2_A + r*G2_LDR + ch*16, g_wb + (size_t)r*COUT_ + ch*8);
    }
    CPA_COMMIT();

    for (int t = 0; t < 16; t++){
        const uint32_t base = sb + (t & 1)*G2_CHUNK;
        if (t < 15){
            const int k1 = (t+1)*64;
            const uint32_t nb = sb + ((t+1) & 1)*G2_CHUNK;
            for (int i = tid; i < 64*8; i += 128){
                int r = i >> 3, ch = i & 7;
                cpa16(nb + 0*G2_A + r*G2_LDR + ch*16, g_ca + (size_t)(bn0+r)*CAT_ + k1 + ch*8);
                cpa16(nb + 1*G2_A + r*G2_LDR + ch*16, g_cb + (size_t)(bn0+r)*CAT_ + k1 + ch*8);
                cpa16(nb + 2*G2_A + r*G2_LDR + ch*16, g_wa + (size_t)(k1+r)*COUT_ + ch*8);
                cpa16(nb + 3*G2_A + r*G2_LDR + ch*16, g_wb + (size_t)(k1+r)*COUT_ + ch*8);
            }
            CPA_COMMIT();
            CPA_WAIT(1);
        } else {
            CPA_WAIT(0);
        }
        __syncthreads();

        // A fragments
        uint32_t aa[4][4], ab[4][4];
        const int rowA = w*16 + (lane & 15);
        const int colA = (lane >> 4) * 8;
#pragma unroll
        for (int kt = 0; kt < 4; kt++){
            ldsm4(aa[kt][0], aa[kt][1], aa[kt][2], aa[kt][3], base + 0*G2_A + rowA*G2_LDR + (kt*16 + colA)*2);
            ldsm4(ab[kt][0], ab[kt][1], ab[kt][2], ab[kt][3], base + 1*G2_A + rowA*G2_LDR + (kt*16 + colA)*2);
        }
        // W fragments + mma
        const int rV = (lane & 7) + ((lane & 8) ? 8 : 0);
        const int cV8 = (lane >> 4) * 8;
#pragma unroll
        for (int ng = 0; ng < 4; ng++){
#pragma unroll
            for (int kt = 0; kt < 4; kt++){
                uint32_t wa0, wa1, wa2, wa3, wb0, wb1, wb2, wb3;
                ldsm4t(wa0, wa1, wa2, wa3, base + 2*G2_A + (kt*16 + rV)*G2_LDR + (ng*16 + cV8)*2);
                ldsm4t(wb0, wb1, wb2, wb3, base + 3*G2_A + (kt*16 + rV)*G2_LDR + (ng*16 + cV8)*2);
                mma16816(o[ng*2],   aa[kt], wa0, wa1);
                mma16816(o[ng*2],   aa[kt], wb0, wb1);
                mma16816(o[ng*2],   ab[kt], wa0, wa1);
                mma16816(o[ng*2+1], aa[kt], wa2, wa3);
                mma16816(o[ng*2+1], aa[kt], wb2, wb3);
                mma16816(o[ng*2+1], ab[kt], wa2, wa3);
            }
        }
        __syncthreads();
    }

    const int g = lane >> 2, q4 = lane & 3;
    const size_t r0 = (size_t)(bn0 + w*16 + g)*COUT_;
    const size_t r1 = (size_t)(bn0 + w*16 + g + 8)*COUT_;
#pragma unroll
    for (int nt = 0; nt < 8; nt++){
        int c = nt*8 + 2*q4;
        uint32_t ua, ub;
        hsplit2(o[nt][0], o[nt][1], ua, ub);
        *(uint32_t*)(g_ha + r0 + c) = ua;
        *(uint32_t*)(g_hb + r0 + c) = ub;
        hsplit2(o[nt][2], o[nt][3], ua, ub);
        *(uint32_t*)(g_ha + r1 + c) = ua;
        *(uint32_t*)(g_hb + r1 + c) = ub;
    }
}

extern "C" void kernel_launch(void* const* d_in, const int* in_sizes, int n_in,
                              void* d_out, int out_size){
    const float* flow_x = (const float*)d_in[0];
    const float* graph  = (const float*)d_in[1];
    const float* Wh     = (const float*)d_in[2];
    const float* bh     = (const float*)d_in[3];
    const float* W_out  = (const float*)d_in[4];
    const float* b_out  = (const float*)d_in[5];
    float* out = (float*)d_out;

    constexpr int SM1 = 2*128*(128+8)*2 + 2*2*64*(128+8)*2;  // 139264
    constexpr int SM2 = 2*64*(64+8)*2  + 2*2*64*(64+8)*2;    // 55296
    constexpr int SMG2 = 2*G2_CHUNK;                         // 73728
    cudaFuncSetAttribute(attn_mma<128,1,128>, cudaFuncAttributeMaxDynamicSharedMemorySize, SM1);
    cudaFuncSetAttribute(attn_mma<64,2,64>,   cudaFuncAttributeMaxDynamicSharedMemorySize, SM2);
    cudaFuncSetAttribute(gemm2_mma,           cudaFuncAttributeMaxDynamicSharedMemorySize, SMG2);

    gemm1_kernel<<<dim3(B_*N_/64, H_), 256>>>(flow_x, Wh);
    graph_bits_kernel<<<128, 256>>>(graph);
    wsplit_kernel<<<128, 256>>>(W_out);
    attn_mma<128,1,128><<<dim3(N_/128, B_, H_), 256, SM1>>>(bh, nullptr);
    gemm2_mma<<<dim3(B_*N_/64), 128, SMG2>>>();
    attn_mma<64,2,64><<<dim3(N_/64, B_, 1), 128, SM2>>>(b_out, out);
}